// round 6
// baseline (speedup 1.0000x reference)
#include <cuda_runtime.h>
#include <cuda_fp16.h>
#include <math.h>

#define Nn 60000
#define Mm 12
#define F0k 92
#define FBk 41
#define Ff 64
#define Hh 128
#define NCc 2000
#define F2 128
#define NM (Nn*Mm)

typedef unsigned long long u64;

// ---------------- f32x2 packed-FMA helpers (sm_100+ PTX) ----------------
__device__ __forceinline__ u64 ffma2(u64 a, u64 b, u64 c){
    u64 d;
    asm("fma.rn.f32x2 %0, %1, %2, %3;" : "=l"(d) : "l"(a), "l"(b), "l"(c));
    return d;
}
__device__ __forceinline__ u64 dup2(float x){
    u64 d; unsigned xi = __float_as_uint(x);
    asm("mov.b64 %0, {%1, %1};" : "=l"(d) : "r"(xi));
    return d;
}
__device__ __forceinline__ float2 unpk(u64 v){
    unsigned lo, hi;
    asm("mov.b64 {%0, %1}, %2;" : "=r"(lo), "=r"(hi) : "l"(v));
    return make_float2(__uint_as_float(lo), __uint_as_float(hi));
}

// ---------------- scratch ----------------
__device__ float g_x[Nn*Ff];
__device__ float g_P[Nn*256];
__device__ __half g_gatedh[(size_t)NM*F2];
__device__ float g_summed[Nn*Ff];
__device__ double g_stats1[2*F2];
__device__ double g_stats2[2*Ff];
__device__ float g_sc1[F2], g_sh1[F2];
__device__ float g_sc2[Ff], g_sh2[Ff];
__device__ float g_crys[NCc*Ff];
__device__ float g_cnt[NCc];

__device__ __forceinline__ float sp(float x){
    return fmaxf(x, 0.f) + __logf(1.f + __expf(-fabsf(x)));
}
__device__ __forceinline__ float sg(float x){
    return __fdividef(1.f, 1.f + __expf(-x));
}

// ---------------- embedding ----------------
__global__ void k_emb(const float* __restrict__ af, const float* __restrict__ W,
                      const float* __restrict__ b){
    __shared__ float s_af[8][F0k];
    int base = blockIdx.x * 8;
    int tid = threadIdx.x;                    // 512
    for(int idx = tid; idx < 8*F0k; idx += 512){
        int a = idx / F0k, k = idx % F0k;
        s_af[a][k] = af[(base+a)*F0k + k];
    }
    __syncthreads();
    int a = tid >> 6, f = tid & 63;
    float acc = b[f];
    #pragma unroll 4
    for(int k = 0; k < F0k; k++) acc += s_af[a][k] * W[k*Ff + f];
    g_x[(base+a)*Ff + f] = acc;
}

__global__ void k_zero_stats(){
    int t = threadIdx.x;
    g_stats1[t] = 0.0;
    if(t < 2*Ff) g_stats2[t] = 0.0;
}

// ------ P = x @ [W1 | W2] (64x128 tile, 256 thr, 4x8, f32x2, occ=3) -------
__global__ void __launch_bounds__(256,3) k_P(const float* __restrict__ Wf){
    __shared__ __align__(16) float Ws[32][128];
    __shared__ __align__(16) float Xt[32][68];
    int half = blockIdx.y;
    int base = blockIdx.x * 64;
    int rem  = Nn - base;
    int tid  = threadIdx.x;                   // 256
    int tx = tid & 15, ty = tid >> 4;         // ty 0..15

    u64 acc2[4][4];
    #pragma unroll
    for(int r=0;r<4;r++)
        #pragma unroll
        for(int c=0;c<4;c++) acc2[r][c]=0ULL;

    for(int kc = 0; kc < 2; kc++){
        for(int i2 = tid; i2 < 32*128; i2 += 256){
            int kk = i2 >> 7, j = i2 & 127;
            Ws[kk][j] = Wf[(half*64 + kc*32 + kk)*128 + j];
        }
        for(int i2 = tid; i2 < 32*64; i2 += 256){
            int a = i2 >> 5, kk = i2 & 31;
            int atom = base + a; if(atom >= Nn) atom = Nn-1;
            Xt[kk][a] = g_x[atom*64 + kc*32 + kk];
        }
        __syncthreads();
        #pragma unroll 2
        for(int k = 0; k < 32; k++){
            float4 a0 = *(const float4*)&Xt[k][ty*4];
            ulonglong2 w0 = *(const ulonglong2*)&Ws[k][tx*4];
            ulonglong2 w1 = *(const ulonglong2*)&Ws[k][64 + tx*4];
            u64 bp[4] = {w0.x, w0.y, w1.x, w1.y};
            float av[4] = {a0.x,a0.y,a0.z,a0.w};
            #pragma unroll
            for(int r=0;r<4;r++){
                u64 ad = dup2(av[r]);
                #pragma unroll
                for(int c=0;c<4;c++) acc2[r][c] = ffma2(ad, bp[c], acc2[r][c]);
            }
        }
        __syncthreads();
    }
    #pragma unroll
    for(int r=0;r<4;r++){
        int row = ty*4 + r;
        if(row < rem){
            float2 v0 = unpk(acc2[r][0]), v1 = unpk(acc2[r][1]);
            float2 v2 = unpk(acc2[r][2]), v3 = unpk(acc2[r][3]);
            float* dst = g_P + (size_t)(base+row)*256 + half*128;
            *(float4*)&dst[tx*4]    = make_float4(v0.x,v0.y,v1.x,v1.y);
            *(float4*)&dst[64+tx*4] = make_float4(v2.x,v2.y,v3.x,v3.y);
        }
    }
}

// -- edge GEMM + P adds + bias + BN1 stats (64x128 tile, 4x8, f32x2, occ=3) --
__global__ void __launch_bounds__(256,3) k_Q(const float* __restrict__ nbr,
                    const int* __restrict__ idx,
                    const float* __restrict__ Wf, const float* __restrict__ bias){
    __shared__ __align__(16) float Ws[41][128];
    __shared__ __align__(16) float At[41][68];
    __shared__ float reds[128], redss[128];
    int tid = threadIdx.x;                    // 256
    int row0 = blockIdx.x * 64;
    int tx = tid & 15, ty = tid >> 4;         // ty 0..15
    const float* W3 = Wf + 128*128;

    for(int i2 = tid; i2 < 41*128; i2 += 256){
        int k = i2 >> 7, j = i2 & 127;
        Ws[k][j] = W3[k*128 + j];
    }
    for(int i2 = tid; i2 < 64*41; i2 += 256){
        int r = i2 / 41, k = i2 % 41;
        At[k][r] = nbr[(size_t)(row0 + r)*41 + k];
    }
    if(tid < 128){ reds[tid] = 0.f; redss[tid] = 0.f; }
    __syncthreads();

    u64 acc2[4][4];
    #pragma unroll
    for(int r=0;r<4;r++)
        #pragma unroll
        for(int c=0;c<4;c++) acc2[r][c]=0ULL;

    #pragma unroll 2
    for(int k = 0; k < 41; k++){
        float4 a0 = *(const float4*)&At[k][ty*4];
        ulonglong2 w0 = *(const ulonglong2*)&Ws[k][tx*4];
        ulonglong2 w1 = *(const ulonglong2*)&Ws[k][64 + tx*4];
        u64 bp[4] = {w0.x, w0.y, w1.x, w1.y};
        float av[4] = {a0.x,a0.y,a0.z,a0.w};
        #pragma unroll
        for(int r=0;r<4;r++){
            u64 ad = dup2(av[r]);
            #pragma unroll
            for(int c=0;c<4;c++) acc2[r][c] = ffma2(ad, bp[c], acc2[r][c]);
        }
    }
    __syncthreads();

    // overlay epilogue data in At storage (64 rows span <=6 atoms)
    float (*sP1)[128] = (float(*)[128])&At[0][0];        // 6*128 floats
    int*   sIdx       = (int*)(&At[0][0] + 6*128);       // 64 ints
    int a0atom = row0 / Mm;
    for(int j = tid; j < 6*128; j += 256){
        int at = j >> 7, col = j & 127;
        int atom = a0atom + at; if(atom >= Nn) atom = Nn-1;
        sP1[at][col] = g_P[(size_t)atom*256 + col];
    }
    if(tid < 64) sIdx[tid] = idx[row0 + tid];
    __syncthreads();

    float4 bb0 = *(const float4*)&bias[tx*4];
    float4 bb1 = *(const float4*)&bias[64 + tx*4];
    float bj[8] = {bb0.x,bb0.y,bb0.z,bb0.w,bb1.x,bb1.y,bb1.z,bb1.w};

    float s[8], ssq[8];
    #pragma unroll
    for(int c=0;c<8;c++){ s[c]=0.f; ssq[c]=0.f; }

    #pragma unroll
    for(int r=0;r<4;r++){
        int row = ty*4 + r;
        int g = row0 + row;
        int irel = (g / Mm) - a0atom;
        int nb = sIdx[row];
        const float* p2p = g_P + (size_t)nb*256 + 128;
        float4 p1a = *(const float4*)&sP1[irel][tx*4];
        float4 p1b = *(const float4*)&sP1[irel][64+tx*4];
        float4 p2a = *(const float4*)&p2p[tx*4];
        float4 p2b = *(const float4*)&p2p[64+tx*4];
        float pv[8] = {p1a.x+p2a.x, p1a.y+p2a.y, p1a.z+p2a.z, p1a.w+p2a.w,
                       p1b.x+p2b.x, p1b.y+p2b.y, p1b.z+p2b.z, p1b.w+p2b.w};
        float2 v0 = unpk(acc2[r][0]), v1 = unpk(acc2[r][1]);
        float2 v2 = unpk(acc2[r][2]), v3 = unpk(acc2[r][3]);
        float am[8] = {v0.x,v0.y,v1.x,v1.y,v2.x,v2.y,v3.x,v3.y};
        float out[8];
        #pragma unroll
        for(int c=0;c<8;c++){
            float v = am[c] + bj[c] + pv[c];
            out[c] = v; s[c] += v; ssq[c] += v*v;
        }
        __half2 h0 = __floats2half2_rn(out[0], out[1]);
        __half2 h1 = __floats2half2_rn(out[2], out[3]);
        __half2 h2v = __floats2half2_rn(out[4], out[5]);
        __half2 h3 = __floats2half2_rn(out[6], out[7]);
        __half* dst = g_gatedh + (size_t)g*128;
        *(uint2*)&dst[tx*4]    = make_uint2(*(unsigned*)&h0, *(unsigned*)&h1);
        *(uint2*)&dst[64+tx*4] = make_uint2(*(unsigned*)&h2v, *(unsigned*)&h3);
    }
    #pragma unroll
    for(int c=0;c<8;c++){
        int col = (c<4) ? (tx*4+c) : (64 + tx*4 + (c-4));
        atomicAdd(&reds [col], s[c]);
        atomicAdd(&redss[col], ssq[c]);
    }
    __syncthreads();
    if(tid < 128){
        atomicAdd(&g_stats1[tid],       (double)reds[tid]);
        atomicAdd(&g_stats1[128 + tid], (double)redss[tid]);
    }
}

__global__ void k_fin1(const float* __restrict__ g1, const float* __restrict__ be1){
    int j = threadIdx.x;                      // 128
    double n = (double)NM;
    double mu = g_stats1[j] / n;
    double var = g_stats1[128 + j] / n - mu*mu;
    float r = rsqrtf((float)var + 1e-5f);
    float sc = g1[j] * r;
    g_sc1[j] = sc;
    g_sh1[j] = be1[j] - (float)mu * sc;
}

// ------- BN1 apply + sigmoid*softplus + sum over M + BN2 stats (fp16 in) ----
__global__ void k_B(){
    __shared__ float rs[64], rss[64];
    int tid = threadIdx.x;                    // 256; 32 atoms/block
    int fg = (tid & 15) * 4;
    int s  = tid >> 4;                        // 0..15, 2 atoms each
    int base = blockIdx.x * 32 + s*2;
    if(tid < 64){ rs[tid] = 0.f; rss[tid] = 0.f; }
    float4 scf = *(const float4*)&g_sc1[fg];
    float4 shf = *(const float4*)&g_sh1[fg];
    float4 scc = *(const float4*)&g_sc1[64+fg];
    float4 shc = *(const float4*)&g_sh1[64+fg];
    float sc_f[4] = {scf.x,scf.y,scf.z,scf.w};
    float sh_f[4] = {shf.x,shf.y,shf.z,shf.w};
    float sc_c[4] = {scc.x,scc.y,scc.z,scc.w};
    float sh_c[4] = {shc.x,shc.y,shc.z,shc.w};
    __syncthreads();

    float ts[4] = {0,0,0,0}, tss[4] = {0,0,0,0};
    #pragma unroll
    for(int a = 0; a < 2; a++){
        int i = base + a;
        const __half* gp = g_gatedh + (size_t)i*Mm*F2;
        float acc[4] = {0,0,0,0};
        #pragma unroll
        for(int m = 0; m < Mm; m++){
            uint2 uf = *(const uint2*)&gp[m*F2 + fg];
            uint2 uc = *(const uint2*)&gp[m*F2 + 64 + fg];
            float2 f01 = __half22float2(*(__half2*)&uf.x);
            float2 f23 = __half22float2(*(__half2*)&uf.y);
            float2 c01 = __half22float2(*(__half2*)&uc.x);
            float2 c23 = __half22float2(*(__half2*)&uc.y);
            float f0[4] = {f01.x, f01.y, f23.x, f23.y};
            float c0[4] = {c01.x, c01.y, c23.x, c23.y};
            #pragma unroll
            for(int c=0;c<4;c++)
                acc[c] += sg(f0[c]*sc_f[c]+sh_f[c]) * sp(c0[c]*sc_c[c]+sh_c[c]);
        }
        *(float4*)&g_summed[i*64 + fg] = make_float4(acc[0],acc[1],acc[2],acc[3]);
        #pragma unroll
        for(int c=0;c<4;c++){ ts[c] += acc[c]; tss[c] += acc[c]*acc[c]; }
    }
    #pragma unroll
    for(int c=0;c<4;c++){
        atomicAdd(&rs [fg+c], ts[c]);
        atomicAdd(&rss[fg+c], tss[c]);
    }
    __syncthreads();
    if(tid < 64){
        atomicAdd(&g_stats2[tid],      (double)rs[tid]);
        atomicAdd(&g_stats2[64 + tid], (double)rss[tid]);
    }
}

__global__ void k_fin2(const float* __restrict__ g2, const float* __restrict__ be2){
    int j = threadIdx.x;                      // 64
    double n = (double)Nn;
    double mu = g_stats2[j] / n;
    double var = g_stats2[64 + j] / n - mu*mu;
    float r = rsqrtf((float)var + 1e-5f);
    float sc = g2[j] * r;
    g_sc2[j] = sc;
    g_sh2[j] = be2[j] - (float)mu * sc;
}

__global__ void k_upd(){
    int id = blockIdx.x*256 + threadIdx.x;    // N*16 threads (float4 each)
    int fg = (id & 15) * 4;
    float4 xv = *(const float4*)&g_x[id*4];
    float4 sv = *(const float4*)&g_summed[id*4];
    float4 sc = *(const float4*)&g_sc2[fg];
    float4 sh = *(const float4*)&g_sh2[fg];
    float4 o;
    o.x = sp(xv.x + sv.x*sc.x + sh.x);
    o.y = sp(xv.y + sv.y*sc.y + sh.y);
    o.z = sp(xv.z + sv.z*sc.z + sh.z);
    o.w = sp(xv.w + sv.w*sc.w + sh.w);
    *(float4*)&g_x[id*4] = o;
}

// ---------------- pooling + head ----------------
__global__ void k_pool_zero(){
    int id = blockIdx.x*256 + threadIdx.x;
    if(id < NCc*Ff) g_crys[id] = 0.f;
    else if(id < NCc*Ff + NCc) g_cnt[id - NCc*Ff] = 0.f;
}

__global__ void k_pool(const int* __restrict__ cidx){
    int id = blockIdx.x*256 + threadIdx.x;    // N*64 threads
    int i = id >> 6, f = id & 63;
    int c = cidx[i];
    atomicAdd(&g_crys[c*64 + f], g_x[id]);
    if(f == 0) atomicAdd(&g_cnt[c], 1.f);
}

__global__ void k_head(const float* __restrict__ W_fc, const float* __restrict__ b_fc,
                       const float* __restrict__ W_out, const float* __restrict__ b_out,
                       float* __restrict__ out){
    __shared__ float t[64];
    __shared__ float hred[128];
    int c = blockIdx.x, th = threadIdx.x;     // 128
    if(th < 64){
        float cn = fmaxf(g_cnt[c], 1.f);
        t[th] = sp(g_crys[c*64 + th] / cn);
    }
    __syncthreads();
    float acc = b_fc[th];
    #pragma unroll 4
    for(int f = 0; f < 64; f++) acc += t[f] * W_fc[f*128 + th];
    hred[th] = sp(acc) * W_out[th];
    __syncthreads();
    for(int o = 64; o > 0; o >>= 1){
        if(th < o) hred[th] += hred[th + o];
        __syncthreads();
    }
    if(th == 0) out[c] = hred[0] + b_out[0];
}

// ---------------- launcher ----------------
extern "C" void kernel_launch(void* const* d_in, const int* in_sizes, int n_in,
                              void* d_out, int out_size){
    const float* atom_fea = (const float*)d_in[0];
    const float* nbr_fea  = (const float*)d_in[1];
    const int*   nbr_idx  = (const int*)  d_in[2];
    const int*   cidx     = (const int*)  d_in[3];
    const float* W_emb    = (const float*)d_in[4];
    const float* b_emb    = (const float*)d_in[5];
    const float* W_full   = (const float*)d_in[6];
    const float* b_full   = (const float*)d_in[7];
    const float* g1       = (const float*)d_in[8];
    const float* be1      = (const float*)d_in[9];
    const float* g2       = (const float*)d_in[10];
    const float* be2      = (const float*)d_in[11];
    const float* W_fc     = (const float*)d_in[12];
    const float* b_fc     = (const float*)d_in[13];
    const float* W_out    = (const float*)d_in[14];
    const float* b_out    = (const float*)d_in[15];
    float* out = (float*)d_out;

    k_emb<<<Nn/8, 512>>>(atom_fea, W_emb, b_emb);

    for(int l = 0; l < 3; l++){
        k_zero_stats<<<1, 256>>>();
        dim3 gp((Nn + 63)/64, 2);
        k_P<<<gp, 256>>>(W_full + (size_t)l*169*128);
        k_Q<<<NM/64, 256>>>(nbr_fea, nbr_idx, W_full + (size_t)l*169*128,
                            b_full + l*128);
        k_fin1<<<1, 128>>>(g1 + l*128, be1 + l*128);
        k_B<<<Nn/32, 256>>>();
        k_fin2<<<1, 64>>>(g2 + l*64, be2 + l*64);
        k_upd<<<(Nn*16)/256, 256>>>();
    }

    k_pool_zero<<<(NCc*Ff + NCc + 255)/256, 256>>>();
    k_pool<<<(Nn*Ff)/256, 256>>>(cidx);
    k_head<<<NCc, 128>>>(W_fc, b_fc, W_out, b_out, out);
}

// round 8
// speedup vs baseline: 1.1738x; 1.1738x over previous
#include <cuda_runtime.h>
#include <cuda_fp16.h>
#include <math.h>

#define Nn 60000
#define Mm 12
#define F0k 92
#define FBk 41
#define Ff 64
#define Hh 128
#define NCc 2000
#define F2 128
#define NM (Nn*Mm)

typedef unsigned long long u64;

// ---------------- f32x2 packed-FMA helpers (sm_100+ PTX) ----------------
__device__ __forceinline__ u64 ffma2(u64 a, u64 b, u64 c){
    u64 d;
    asm("fma.rn.f32x2 %0, %1, %2, %3;" : "=l"(d) : "l"(a), "l"(b), "l"(c));
    return d;
}
__device__ __forceinline__ u64 dup2(float x){
    u64 d; unsigned xi = __float_as_uint(x);
    asm("mov.b64 %0, {%1, %1};" : "=l"(d) : "r"(xi));
    return d;
}
__device__ __forceinline__ float2 unpk(u64 v){
    unsigned lo, hi;
    asm("mov.b64 {%0, %1}, %2;" : "=r"(lo), "=r"(hi) : "l"(v));
    return make_float2(__uint_as_float(lo), __uint_as_float(hi));
}
__device__ __forceinline__ void cpa16(unsigned dst, const void* src){
    asm volatile("cp.async.ca.shared.global [%0], [%1], 16;" :: "r"(dst), "l"(src) : "memory");
}

// ---------------- scratch ----------------
__device__ float g_x[Nn*Ff];
__device__ __half g_Ph[Nn*256];                   // fp16 [P1|P2] per atom
__device__ __half g_gatedh[(size_t)NM*F2];
__device__ float g_summed[Nn*Ff];
__device__ double g_stats1[2*F2];
__device__ double g_stats2[2*Ff];
__device__ float g_sc1[F2], g_sh1[F2];
__device__ float g_sc2[Ff], g_sh2[Ff];
__device__ float g_crys[NCc*Ff];
__device__ float g_cnt[NCc];

__device__ __forceinline__ float sp(float x){
    return fmaxf(x, 0.f) + __logf(1.f + __expf(-fabsf(x)));
}
__device__ __forceinline__ float sg(float x){
    return __fdividef(1.f, 1.f + __expf(-x));
}

// ---------------- embedding ----------------
__global__ void k_emb(const float* __restrict__ af, const float* __restrict__ W,
                      const float* __restrict__ b){
    __shared__ float s_af[8][F0k];
    int base = blockIdx.x * 8;
    int tid = threadIdx.x;                    // 512
    for(int idx = tid; idx < 8*F0k; idx += 512){
        int a = idx / F0k, k = idx % F0k;
        s_af[a][k] = af[(base+a)*F0k + k];
    }
    __syncthreads();
    int a = tid >> 6, f = tid & 63;
    float acc = b[f];
    #pragma unroll 4
    for(int k = 0; k < F0k; k++) acc += s_af[a][k] * W[k*Ff + f];
    g_x[(base+a)*Ff + f] = acc;
}

__global__ void k_zero_stats(){
    int t = threadIdx.x;
    g_stats1[t] = 0.0;
    if(t < 2*Ff) g_stats2[t] = 0.0;
}

// ------ P = x @ [W1 | W2] (128x128 tile, 256 thr, 8x8, f32x2), fp16 out ----
__global__ void __launch_bounds__(256,2) k_P(const float* __restrict__ Wf){
    __shared__ __align__(16) float Ws[32][128];
    __shared__ __align__(16) float Xt[32][132];
    int hf = blockIdx.y;
    int base = blockIdx.x * 128;
    int rem  = Nn - base;
    int tid  = threadIdx.x;                   // 256
    int tx = tid & 15, ty = tid >> 4;

    u64 acc2[8][4];
    #pragma unroll
    for(int r=0;r<8;r++)
        #pragma unroll
        for(int c=0;c<4;c++) acc2[r][c]=0ULL;

    for(int kc = 0; kc < 2; kc++){
        for(int i2 = tid; i2 < 32*128; i2 += 256){
            int kk = i2 >> 7, j = i2 & 127;
            Ws[kk][j] = Wf[(hf*64 + kc*32 + kk)*128 + j];
        }
        for(int i2 = tid; i2 < 32*128; i2 += 256){
            int a = i2 >> 5, kk = i2 & 31;
            int atom = base + a; if(atom >= Nn) atom = Nn-1;
            Xt[kk][a] = g_x[atom*64 + kc*32 + kk];
        }
        __syncthreads();
        #pragma unroll 2
        for(int k = 0; k < 32; k++){
            float4 a0 = *(const float4*)&Xt[k][ty*4];
            float4 a1 = *(const float4*)&Xt[k][64 + ty*4];
            ulonglong2 w0 = *(const ulonglong2*)&Ws[k][tx*4];
            ulonglong2 w1 = *(const ulonglong2*)&Ws[k][64 + tx*4];
            u64 bp[4] = {w0.x, w0.y, w1.x, w1.y};
            float av[8] = {a0.x,a0.y,a0.z,a0.w,a1.x,a1.y,a1.z,a1.w};
            #pragma unroll
            for(int r=0;r<8;r++){
                u64 ad = dup2(av[r]);
                #pragma unroll
                for(int c=0;c<4;c++) acc2[r][c] = ffma2(ad, bp[c], acc2[r][c]);
            }
        }
        __syncthreads();
    }
    #pragma unroll
    for(int r=0;r<8;r++){
        int row = (r<4) ? (ty*4+r) : (64 + ty*4 + (r-4));
        if(row < rem){
            float2 v0 = unpk(acc2[r][0]), v1 = unpk(acc2[r][1]);
            float2 v2 = unpk(acc2[r][2]), v3 = unpk(acc2[r][3]);
            __half2 h0 = __floats2half2_rn(v0.x, v0.y);
            __half2 h1 = __floats2half2_rn(v1.x, v1.y);
            __half2 h2 = __floats2half2_rn(v2.x, v2.y);
            __half2 h3 = __floats2half2_rn(v3.x, v3.y);
            __half* dst = g_Ph + (size_t)(base+row)*256 + hf*128;
            *(uint2*)&dst[tx*4]    = make_uint2(*(unsigned*)&h0, *(unsigned*)&h1);
            *(uint2*)&dst[64+tx*4] = make_uint2(*(unsigned*)&h2, *(unsigned*)&h3);
        }
    }
}

// dynamic smem layout for k_Q (bytes)
#define OFF_WS    0                     // 41*128 f32 = 20992
#define OFF_AT    20992                 // 41*132 f32 = 21648
#define OFF_SP2   42640                 // 128*128 fp16 = 32768
#define OFF_SP1   75408                 // 12*128 fp16 = 3072
#define OFF_SIDX  78480                 // 128 int = 512
#define OFF_REDS  78992                 // 128 f32
#define OFF_REDSS 79504                 // 128 f32
#define SMEMQ     80128

// -- edge GEMM + P adds + bias + BN1 stats; P1/P2 prefetched via cp.async ----
__global__ void __launch_bounds__(256,2) k_Q(const float* __restrict__ nbr,
                    const int* __restrict__ idx,
                    const float* __restrict__ Wf, const float* __restrict__ bias){
    extern __shared__ __align__(16) char smraw[];
    float* Ws   = (float*)(smraw + OFF_WS);          // [41][128]
    float* At   = (float*)(smraw + OFF_AT);          // [41][132]
    __half* sP2 = (__half*)(smraw + OFF_SP2);        // [128][128]
    __half* sP1 = (__half*)(smraw + OFF_SP1);        // [12][128]
    int*  sIdx  = (int*)(smraw + OFF_SIDX);
    float* reds = (float*)(smraw + OFF_REDS);
    float* redss= (float*)(smraw + OFF_REDSS);
    unsigned sbase = (unsigned)__cvta_generic_to_shared(smraw);

    int tid = threadIdx.x;                    // 256
    int row0 = blockIdx.x * 128;
    int tx = tid & 15, ty = tid >> 4;
    int a0atom = row0 / Mm;
    const float* W3 = Wf + 128*128;

    // ---- prefetch P2 (gather) and P1 into shared, async ----
    if(tid < 128){
        int nb = idx[row0 + tid];
        sIdx[tid] = nb;
        const __half* src = g_Ph + (size_t)nb*256 + 128;
        unsigned dst = sbase + OFF_SP2 + tid*256;
        #pragma unroll
        for(int c = 0; c < 16; c++) cpa16(dst + c*16, src + c*8);
    } else {
        int t2 = tid - 128;                   // 0..127; 12*16=192 chunks needed
        for(int j = t2; j < 192; j += 128){
            int at = j >> 4, c = j & 15;
            int atom = a0atom + at; if(atom >= Nn) atom = Nn-1;
            cpa16(sbase + OFF_SP1 + at*256 + c*16,
                  g_Ph + (size_t)atom*256 + c*8);
        }
    }
    asm volatile("cp.async.commit_group;" ::: "memory");

    // ---- stage W and A-transpose ----
    for(int i2 = tid; i2 < 41*128; i2 += 256){
        int k = i2 >> 7, j = i2 & 127;
        Ws[k*128 + j] = W3[k*128 + j];
    }
    for(int i2 = tid; i2 < 128*41; i2 += 256){
        int r = i2 / 41, k = i2 % 41;
        At[k*132 + r] = nbr[(size_t)(row0 + r)*41 + k];
    }
    if(tid < 128){ reds[tid] = 0.f; redss[tid] = 0.f; }
    __syncthreads();

    u64 acc2[8][4];
    #pragma unroll
    for(int r=0;r<8;r++)
        #pragma unroll
        for(int c=0;c<4;c++) acc2[r][c]=0ULL;

    #pragma unroll 2
    for(int k = 0; k < 41; k++){
        float4 a0 = *(const float4*)&At[k*132 + ty*4];
        float4 a1 = *(const float4*)&At[k*132 + 64 + ty*4];
        ulonglong2 w0 = *(const ulonglong2*)&Ws[k*128 + tx*4];
        ulonglong2 w1 = *(const ulonglong2*)&Ws[k*128 + 64 + tx*4];
        u64 bp[4] = {w0.x, w0.y, w1.x, w1.y};
        float av[8] = {a0.x,a0.y,a0.z,a0.w,a1.x,a1.y,a1.z,a1.w};
        #pragma unroll
        for(int r=0;r<8;r++){
            u64 ad = dup2(av[r]);
            #pragma unroll
            for(int c=0;c<4;c++) acc2[r][c] = ffma2(ad, bp[c], acc2[r][c]);
        }
    }
    asm volatile("cp.async.wait_all;" ::: "memory");
    __syncthreads();

    float4 bb0 = *(const float4*)&bias[tx*4];
    float4 bb1 = *(const float4*)&bias[64 + tx*4];
    float bj[8] = {bb0.x,bb0.y,bb0.z,bb0.w,bb1.x,bb1.y,bb1.z,bb1.w};

    float s[8], ssq[8];
    #pragma unroll
    for(int c=0;c<8;c++){ s[c]=0.f; ssq[c]=0.f; }

    #pragma unroll
    for(int r=0;r<8;r++){
        int row = (r<4) ? (ty*4+r) : (64 + ty*4 + (r-4));
        int g = row0 + row;
        int irel = (g / Mm) - a0atom;
        uint2 ua = *(const uint2*)&sP1[irel*128 + tx*4];
        uint2 ub = *(const uint2*)&sP1[irel*128 + 64 + tx*4];
        uint2 va = *(const uint2*)&sP2[row*128 + tx*4];
        uint2 vb = *(const uint2*)&sP2[row*128 + 64 + tx*4];
        float2 p1a = __half22float2(*(__half2*)&ua.x);
        float2 p1b = __half22float2(*(__half2*)&ua.y);
        float2 p1c = __half22float2(*(__half2*)&ub.x);
        float2 p1d = __half22float2(*(__half2*)&ub.y);
        float2 p2a = __half22float2(*(__half2*)&va.x);
        float2 p2b = __half22float2(*(__half2*)&va.y);
        float2 p2c = __half22float2(*(__half2*)&vb.x);
        float2 p2d = __half22float2(*(__half2*)&vb.y);
        float pv[8] = {p1a.x+p2a.x, p1a.y+p2a.y, p1b.x+p2b.x, p1b.y+p2b.y,
                       p1c.x+p2c.x, p1c.y+p2c.y, p1d.x+p2d.x, p1d.y+p2d.y};
        float2 v0 = unpk(acc2[r][0]), v1 = unpk(acc2[r][1]);
        float2 v2 = unpk(acc2[r][2]), v3 = unpk(acc2[r][3]);
        float am[8] = {v0.x,v0.y,v1.x,v1.y,v2.x,v2.y,v3.x,v3.y};
        float out[8];
        #pragma unroll
        for(int c=0;c<8;c++){
            float v = am[c] + bj[c] + pv[c];
            out[c] = v; s[c] += v; ssq[c] += v*v;
        }
        __half2 h0 = __floats2half2_rn(out[0], out[1]);
        __half2 h1 = __floats2half2_rn(out[2], out[3]);
        __half2 h2v = __floats2half2_rn(out[4], out[5]);
        __half2 h3 = __floats2half2_rn(out[6], out[7]);
        __half* dst = g_gatedh + (size_t)g*128;
        *(uint2*)&dst[tx*4]    = make_uint2(*(unsigned*)&h0, *(unsigned*)&h1);
        *(uint2*)&dst[64+tx*4] = make_uint2(*(unsigned*)&h2v, *(unsigned*)&h3);
    }
    #pragma unroll
    for(int c=0;c<8;c++){
        int col = (c<4) ? (tx*4+c) : (64 + tx*4 + (c-4));
        atomicAdd(&reds [col], s[c]);
        atomicAdd(&redss[col], ssq[c]);
    }
    __syncthreads();
    if(tid < 128){
        atomicAdd(&g_stats1[tid],       (double)reds[tid]);
        atomicAdd(&g_stats1[128 + tid], (double)redss[tid]);
    }
}

__global__ void k_fin1(const float* __restrict__ g1, const float* __restrict__ be1){
    int j = threadIdx.x;                      // 128
    double n = (double)NM;
    double mu = g_stats1[j] / n;
    double var = g_stats1[128 + j] / n - mu*mu;
    float r = rsqrtf((float)var + 1e-5f);
    float sc = g1[j] * r;
    g_sc1[j] = sc;
    g_sh1[j] = be1[j] - (float)mu * sc;
}

// ------- BN1 apply + sigmoid*softplus + sum over M + BN2 stats (fp16 in) ----
__global__ void k_B(){
    __shared__ float rs[64], rss[64];
    int tid = threadIdx.x;                    // 256; 32 atoms/block
    int fg = (tid & 15) * 4;
    int s  = tid >> 4;                        // 0..15, 2 atoms each
    int base = blockIdx.x * 32 + s*2;
    if(tid < 64){ rs[tid] = 0.f; rss[tid] = 0.f; }
    float4 scf = *(const float4*)&g_sc1[fg];
    float4 shf = *(const float4*)&g_sh1[fg];
    float4 scc = *(const float4*)&g_sc1[64+fg];
    float4 shc = *(const float4*)&g_sh1[64+fg];
    float sc_f[4] = {scf.x,scf.y,scf.z,scf.w};
    float sh_f[4] = {shf.x,shf.y,shf.z,shf.w};
    float sc_c[4] = {scc.x,scc.y,scc.z,scc.w};
    float sh_c[4] = {shc.x,shc.y,shc.z,shc.w};
    __syncthreads();

    float ts[4] = {0,0,0,0}, tss[4] = {0,0,0,0};
    #pragma unroll
    for(int a = 0; a < 2; a++){
        int i = base + a;
        const __half* gp = g_gatedh + (size_t)i*Mm*F2;
        float acc[4] = {0,0,0,0};
        #pragma unroll
        for(int m = 0; m < Mm; m++){
            uint2 uf = *(const uint2*)&gp[m*F2 + fg];
            uint2 uc = *(const uint2*)&gp[m*F2 + 64 + fg];
            float2 f01 = __half22float2(*(__half2*)&uf.x);
            float2 f23 = __half22float2(*(__half2*)&uf.y);
            float2 c01 = __half22float2(*(__half2*)&uc.x);
            float2 c23 = __half22float2(*(__half2*)&uc.y);
            float f0[4] = {f01.x, f01.y, f23.x, f23.y};
            float c0[4] = {c01.x, c01.y, c23.x, c23.y};
            #pragma unroll
            for(int c=0;c<4;c++)
                acc[c] += sg(f0[c]*sc_f[c]+sh_f[c]) * sp(c0[c]*sc_c[c]+sh_c[c]);
        }
        *(float4*)&g_summed[i*64 + fg] = make_float4(acc[0],acc[1],acc[2],acc[3]);
        #pragma unroll
        for(int c=0;c<4;c++){ ts[c] += acc[c]; tss[c] += acc[c]*acc[c]; }
    }
    #pragma unroll
    for(int c=0;c<4;c++){
        atomicAdd(&rs [fg+c], ts[c]);
        atomicAdd(&rss[fg+c], tss[c]);
    }
    __syncthreads();
    if(tid < 64){
        atomicAdd(&g_stats2[tid],      (double)rs[tid]);
        atomicAdd(&g_stats2[64 + tid], (double)rss[tid]);
    }
}

__global__ void k_fin2(const float* __restrict__ g2, const float* __restrict__ be2){
    int j = threadIdx.x;                      // 64
    double n = (double)Nn;
    double mu = g_stats2[j] / n;
    double var = g_stats2[64 + j] / n - mu*mu;
    float r = rsqrtf((float)var + 1e-5f);
    float sc = g2[j] * r;
    g_sc2[j] = sc;
    g_sh2[j] = be2[j] - (float)mu * sc;
}

__global__ void k_upd(){
    int id = blockIdx.x*256 + threadIdx.x;    // N*16 threads (float4 each)
    int fg = (id & 15) * 4;
    float4 xv = *(const float4*)&g_x[id*4];
    float4 sv = *(const float4*)&g_summed[id*4];
    float4 sc = *(const float4*)&g_sc2[fg];
    float4 sh = *(const float4*)&g_sh2[fg];
    float4 o;
    o.x = sp(xv.x + sv.x*sc.x + sh.x);
    o.y = sp(xv.y + sv.y*sc.y + sh.y);
    o.z = sp(xv.z + sv.z*sc.z + sh.z);
    o.w = sp(xv.w + sv.w*sc.w + sh.w);
    *(float4*)&g_x[id*4] = o;
}

// ---------------- pooling + head ----------------
__global__ void k_pool_zero(){
    int id = blockIdx.x*256 + threadIdx.x;
    if(id < NCc*Ff) g_crys[id] = 0.f;
    else if(id < NCc*Ff + NCc) g_cnt[id - NCc*Ff] = 0.f;
}

__global__ void k_pool(const int* __restrict__ cidx){
    int id = blockIdx.x*256 + threadIdx.x;    // N*64 threads
    int i = id >> 6, f = id & 63;
    int c = cidx[i];
    atomicAdd(&g_crys[c*64 + f], g_x[id]);
    if(f == 0) atomicAdd(&g_cnt[c], 1.f);
}

__global__ void k_head(const float* __restrict__ W_fc, const float* __restrict__ b_fc,
                       const float* __restrict__ W_out, const float* __restrict__ b_out,
                       float* __restrict__ out){
    __shared__ float t[64];
    __shared__ float hred[128];
    int c = blockIdx.x, th = threadIdx.x;     // 128
    if(th < 64){
        float cn = fmaxf(g_cnt[c], 1.f);
        t[th] = sp(g_crys[c*64 + th] / cn);
    }
    __syncthreads();
    float acc = b_fc[th];
    #pragma unroll 4
    for(int f = 0; f < 64; f++) acc += t[f] * W_fc[f*128 + th];
    hred[th] = sp(acc) * W_out[th];
    __syncthreads();
    for(int o = 64; o > 0; o >>= 1){
        if(th < o) hred[th] += hred[th + o];
        __syncthreads();
    }
    if(th == 0) out[c] = hred[0] + b_out[0];
}

// ---------------- launcher ----------------
extern "C" void kernel_launch(void* const* d_in, const int* in_sizes, int n_in,
                              void* d_out, int out_size){
    const float* atom_fea = (const float*)d_in[0];
    const float* nbr_fea  = (const float*)d_in[1];
    const int*   nbr_idx  = (const int*)  d_in[2];
    const int*   cidx     = (const int*)  d_in[3];
    const float* W_emb    = (const float*)d_in[4];
    const float* b_emb    = (const float*)d_in[5];
    const float* W_full   = (const float*)d_in[6];
    const float* b_full   = (const float*)d_in[7];
    const float* g1       = (const float*)d_in[8];
    const float* be1      = (const float*)d_in[9];
    const float* g2       = (const float*)d_in[10];
    const float* be2      = (const float*)d_in[11];
    const float* W_fc     = (const float*)d_in[12];
    const float* b_fc     = (const float*)d_in[13];
    const float* W_out    = (const float*)d_in[14];
    const float* b_out    = (const float*)d_in[15];
    float* out = (float*)d_out;

    cudaFuncSetAttribute(k_Q, cudaFuncAttributeMaxDynamicSharedMemorySize, SMEMQ);

    k_emb<<<Nn/8, 512>>>(atom_fea, W_emb, b_emb);

    for(int l = 0; l < 3; l++){
        k_zero_stats<<<1, 256>>>();
        dim3 gp((Nn + 127)/128, 2);
        k_P<<<gp, 256>>>(W_full + (size_t)l*169*128);
        k_Q<<<NM/128, 256, SMEMQ>>>(nbr_fea, nbr_idx,
                                    W_full + (size_t)l*169*128, b_full + l*128);
        k_fin1<<<1, 128>>>(g1 + l*128, be1 + l*128);
        k_B<<<Nn/32, 256>>>();
        k_fin2<<<1, 64>>>(g2 + l*64, be2 + l*64);
        k_upd<<<(Nn*16)/256, 256>>>();
    }

    k_pool_zero<<<(NCc*Ff + NCc + 255)/256, 256>>>();
    k_pool<<<(Nn*Ff)/256, 256>>>(cidx);
    k_head<<<NCc, 128>>>(W_fc, b_fc, W_out, b_out, out);
}

// round 10
// speedup vs baseline: 1.3381x; 1.1399x over previous
#include <cuda_runtime.h>
#include <cuda_fp16.h>
#include <math.h>

#define Nn 60000
#define Mm 12
#define F0k 92
#define FBk 41
#define Ff 64
#define Hh 128
#define NCc 2000
#define F2 128
#define NM (Nn*Mm)

typedef unsigned long long u64;

// ---------------- f32x2 packed-FMA helpers (sm_100+ PTX) ----------------
__device__ __forceinline__ u64 ffma2(u64 a, u64 b, u64 c){
    u64 d;
    asm("fma.rn.f32x2 %0, %1, %2, %3;" : "=l"(d) : "l"(a), "l"(b), "l"(c));
    return d;
}
__device__ __forceinline__ u64 dup2(float x){
    u64 d; unsigned xi = __float_as_uint(x);
    asm("mov.b64 %0, {%1, %1};" : "=l"(d) : "r"(xi));
    return d;
}
__device__ __forceinline__ float2 unpk(u64 v){
    unsigned lo, hi;
    asm("mov.b64 {%0, %1}, %2;" : "=r"(lo), "=r"(hi) : "l"(v));
    return make_float2(__uint_as_float(lo), __uint_as_float(hi));
}
__device__ __forceinline__ void cpa16(unsigned dst, const void* src){
    asm volatile("cp.async.ca.shared.global [%0], [%1], 16;" :: "r"(dst), "l"(src) : "memory");
}
__device__ __forceinline__ void ldmx4(unsigned& r0, unsigned& r1, unsigned& r2,
                                      unsigned& r3, unsigned addr){
    asm volatile("ldmatrix.sync.aligned.m8n8.x4.shared.b16 {%0,%1,%2,%3}, [%4];"
                 : "=r"(r0), "=r"(r1), "=r"(r2), "=r"(r3) : "r"(addr));
}
__device__ __forceinline__ void hmma(float* d, const unsigned* a,
                                     unsigned b0, unsigned b1){
    asm volatile(
        "mma.sync.aligned.m16n8k16.row.col.f32.f16.f16.f32 "
        "{%0,%1,%2,%3}, {%4,%5,%6,%7}, {%8,%9}, {%0,%1,%2,%3};"
        : "+f"(d[0]), "+f"(d[1]), "+f"(d[2]), "+f"(d[3])
        : "r"(a[0]), "r"(a[1]), "r"(a[2]), "r"(a[3]), "r"(b0), "r"(b1));
}
#define SWZ(o) ((o) ^ (((o) >> 3) & 0x70))

// ---------------- scratch ----------------
__device__ float g_x[Nn*Ff];
__device__ __half g_Ph[Nn*256];                   // fp16 [P1|P2] per atom
__device__ __half g_gatedh[(size_t)NM*F2];
__device__ float g_summed[Nn*Ff];
__device__ double g_stats1[2*F2];
__device__ double g_stats2[2*Ff];
__device__ float g_sc1[F2], g_sh1[F2];
__device__ float g_sc2[Ff], g_sh2[Ff];
__device__ float g_crys[NCc*Ff];
__device__ float g_cnt[NCc];

__device__ __forceinline__ float sp(float x){
    return fmaxf(x, 0.f) + __logf(1.f + __expf(-fabsf(x)));
}
__device__ __forceinline__ float sg(float x){
    return __fdividef(1.f, 1.f + __expf(-x));
}

// ---------------- embedding ----------------
__global__ void k_emb(const float* __restrict__ af, const float* __restrict__ W,
                      const float* __restrict__ b){
    __shared__ float s_af[8][F0k];
    int base = blockIdx.x * 8;
    int tid = threadIdx.x;                    // 512
    for(int idx = tid; idx < 8*F0k; idx += 512){
        int a = idx / F0k, k = idx % F0k;
        s_af[a][k] = af[(base+a)*F0k + k];
    }
    __syncthreads();
    int a = tid >> 6, f = tid & 63;
    float acc = b[f];
    #pragma unroll 4
    for(int k = 0; k < F0k; k++) acc += s_af[a][k] * W[k*Ff + f];
    g_x[(base+a)*Ff + f] = acc;
}

__global__ void k_zero_stats(){
    int t = threadIdx.x;
    g_stats1[t] = 0.0;
    if(t < 2*Ff) g_stats2[t] = 0.0;
}

// ------ P = x @ [W1 | W2] (128x128 tile, 256 thr, 8x8, f32x2), fp16 out ----
__global__ void __launch_bounds__(256,2) k_P(const float* __restrict__ Wf){
    __shared__ __align__(16) float Ws[32][128];
    __shared__ __align__(16) float Xt[32][132];
    int hf = blockIdx.y;
    int base = blockIdx.x * 128;
    int rem  = Nn - base;
    int tid  = threadIdx.x;                   // 256
    int tx = tid & 15, ty = tid >> 4;

    u64 acc2[8][4];
    #pragma unroll
    for(int r=0;r<8;r++)
        #pragma unroll
        for(int c=0;c<4;c++) acc2[r][c]=0ULL;

    for(int kc = 0; kc < 2; kc++){
        for(int i2 = tid; i2 < 32*128; i2 += 256){
            int kk = i2 >> 7, j = i2 & 127;
            Ws[kk][j] = Wf[(hf*64 + kc*32 + kk)*128 + j];
        }
        for(int i2 = tid; i2 < 32*128; i2 += 256){
            int a = i2 >> 5, kk = i2 & 31;
            int atom = base + a; if(atom >= Nn) atom = Nn-1;
            Xt[kk][a] = g_x[atom*64 + kc*32 + kk];
        }
        __syncthreads();
        #pragma unroll 2
        for(int k = 0; k < 32; k++){
            float4 a0 = *(const float4*)&Xt[k][ty*4];
            float4 a1 = *(const float4*)&Xt[k][64 + ty*4];
            ulonglong2 w0 = *(const ulonglong2*)&Ws[k][tx*4];
            ulonglong2 w1 = *(const ulonglong2*)&Ws[k][64 + tx*4];
            u64 bp[4] = {w0.x, w0.y, w1.x, w1.y};
            float av[8] = {a0.x,a0.y,a0.z,a0.w,a1.x,a1.y,a1.z,a1.w};
            #pragma unroll
            for(int r=0;r<8;r++){
                u64 ad = dup2(av[r]);
                #pragma unroll
                for(int c=0;c<4;c++) acc2[r][c] = ffma2(ad, bp[c], acc2[r][c]);
            }
        }
        __syncthreads();
    }
    #pragma unroll
    for(int r=0;r<8;r++){
        int row = (r<4) ? (ty*4+r) : (64 + ty*4 + (r-4));
        if(row < rem){
            float2 v0 = unpk(acc2[r][0]), v1 = unpk(acc2[r][1]);
            float2 v2 = unpk(acc2[r][2]), v3 = unpk(acc2[r][3]);
            __half2 h0 = __floats2half2_rn(v0.x, v0.y);
            __half2 h1 = __floats2half2_rn(v1.x, v1.y);
            __half2 h2 = __floats2half2_rn(v2.x, v2.y);
            __half2 h3 = __floats2half2_rn(v3.x, v3.y);
            __half* dst = g_Ph + (size_t)(base+row)*256 + hf*128;
            *(uint2*)&dst[tx*4]    = make_uint2(*(unsigned*)&h0, *(unsigned*)&h1);
            *(uint2*)&dst[64+tx*4] = make_uint2(*(unsigned*)&h2, *(unsigned*)&h3);
        }
    }
}

// ---- k_Q dynamic smem layout (offsets from 1024-aligned base, bytes) ----
#define QOFF_A    0         // A tile: 128 rows x 64 fp16 (SW128) = 16384
#define QOFF_B    16384     // B tile: 128 rows x 64 fp16 (SW128) = 16384
                            // Dsm aliases [0, 33792): 128 x 132 fp16
#define QOFF_SP2  33792     // 128*128 fp16 = 32768
#define QOFF_SP1  66560     // 12*128 fp16 = 3072
#define QOFF_SIDX 69632     // 128 int
#define QOFF_REDS 70144     // 128 f32
#define QOFF_RSS  70656     // 128 f32
#define SMEMQ     (71168 + 1024)

// -- edge GEMM (mma.sync f16) + P adds + bias + BN1 stats -------------------
__global__ void __launch_bounds__(256,2) k_Q(const float* __restrict__ nbr,
                    const int* __restrict__ idx,
                    const float* __restrict__ Wf, const float* __restrict__ bias){
    extern __shared__ __align__(16) char smraw[];
    unsigned sb0 = (unsigned)__cvta_generic_to_shared(smraw);
    unsigned sb  = (sb0 + 1023u) & ~1023u;
    char* smem = smraw + (sb - sb0);

    __half* Dsm = (__half*)(smem);                 // post-MMA alias of A|B
    __half* sP2 = (__half*)(smem + QOFF_SP2);
    __half* sP1 = (__half*)(smem + QOFF_SP1);
    int*  sIdx  = (int*)(smem + QOFF_SIDX);
    float* reds = (float*)(smem + QOFF_REDS);
    float* redss= (float*)(smem + QOFF_RSS);

    int tid = threadIdx.x;                    // 256
    int wid = tid >> 5, lane = tid & 31;
    int row0 = blockIdx.x * 128;
    int tx = tid & 15, ty = tid >> 4;
    int a0atom = row0 / Mm;
    const float* W3 = Wf + 128*128;

    // ---- prefetch P2 (gather) and P1 into shared, async ----
    if(tid < 128){
        int nb = idx[row0 + tid];
        sIdx[tid] = nb;
        const __half* src = g_Ph + (size_t)nb*256 + 128;
        unsigned dst = sb + QOFF_SP2 + tid*256;
        #pragma unroll
        for(int c = 0; c < 16; c++) cpa16(dst + c*16, src + c*8);
    } else {
        int t2 = tid - 128;                   // 12*16=192 chunks over 128 threads
        for(int j = t2; j < 192; j += 128){
            int at = j >> 4, c = j & 15;
            int atom = a0atom + at; if(atom >= Nn) atom = Nn-1;
            cpa16(sb + QOFF_SP1 + at*256 + c*16,
                  g_Ph + (size_t)atom*256 + c*8);
        }
    }
    asm volatile("cp.async.commit_group;" ::: "memory");

    // ---- zero A|B tiles (zero-pad K 41..63) ----
    float4 z4 = make_float4(0.f,0.f,0.f,0.f);
    for(int i = tid; i < 2048; i += 256)
        *(float4*)(smem + (size_t)i*16) = z4;
    __syncthreads();

    // ---- stage A: nbr -> fp16 SW128 (rows=edges, K-major, 128B rows) ----
    for(int i2 = tid; i2 < 128*41; i2 += 256){
        int r = i2 / 41, k = i2 % 41;
        __half h = __float2half_rn(nbr[(size_t)(row0 + r)*41 + k]);
        *(__half*)(smem + QOFF_A + SWZ((unsigned)(r*128 + k*2))) = h;
    }
    // ---- stage B: W3^T -> fp16 SW128 (rows=N cols, K-major) ----
    for(int i2 = tid; i2 < 41*128; i2 += 256){
        int k = i2 >> 7, n = i2 & 127;
        __half h = __float2half_rn(W3[k*128 + n]);
        *(__half*)(smem + QOFF_B + SWZ((unsigned)(n*128 + k*2))) = h;
    }
    if(tid < 128){ reds[tid] = 0.f; redss[tid] = 0.f; }
    __syncthreads();

    // ---- HMMA mainloop: warp tile 32 rows x 64 cols; K=48 in 3 steps ----
    int m0 = (wid & 3) * 32;
    int n0 = (wid >> 2) * 64;
    float acc[2][8][4];
    #pragma unroll
    for(int mt=0;mt<2;mt++)
        #pragma unroll
        for(int nt=0;nt<8;nt++)
            #pragma unroll
            for(int c=0;c<4;c++) acc[mt][nt][c]=0.f;

    int l7  = lane & 7;
    int aRowSel = (lane & 8) ? 8 : 0;
    int aColSel = (lane & 16) ? 8 : 0;
    int bRowSel = (lane & 16) ? 8 : 0;
    int bColSel = (lane & 8) ? 8 : 0;

    #pragma unroll
    for(int ks = 0; ks < 3; ks++){
        int k0 = ks*16;
        unsigned a[2][4];
        #pragma unroll
        for(int mt = 0; mt < 2; mt++){
            int r = m0 + mt*16 + l7 + aRowSel;
            unsigned addr = sb + QOFF_A + SWZ((unsigned)(r*128 + (k0 + aColSel)*2));
            ldmx4(a[mt][0], a[mt][1], a[mt][2], a[mt][3], addr);
        }
        #pragma unroll
        for(int ntp = 0; ntp < 4; ntp++){
            int n = n0 + ntp*16 + l7 + bRowSel;
            unsigned addr = sb + QOFF_B + SWZ((unsigned)(n*128 + (k0 + bColSel)*2));
            unsigned b0, b1, b2, b3;
            ldmx4(b0, b1, b2, b3, addr);
            hmma(acc[0][2*ntp],   a[0], b0, b1);
            hmma(acc[0][2*ntp+1], a[0], b2, b3);
            hmma(acc[1][2*ntp],   a[1], b0, b1);
            hmma(acc[1][2*ntp+1], a[1], b2, b3);
        }
    }
    __syncthreads();                          // A/B reads done; Dsm can alias

    // ---- stage D -> Dsm (fp16, 132-half padded rows) ----
    {
        int rl = lane >> 2, cq = (lane & 3)*2;
        #pragma unroll
        for(int mt = 0; mt < 2; mt++){
            int rlo = m0 + mt*16 + rl;
            #pragma unroll
            for(int nt = 0; nt < 8; nt++){
                int col = n0 + nt*8 + cq;
                __half2 hlo = __floats2half2_rn(acc[mt][nt][0], acc[mt][nt][1]);
                __half2 hhi = __floats2half2_rn(acc[mt][nt][2], acc[mt][nt][3]);
                *(unsigned*)&Dsm[rlo*132 + col]     = *(unsigned*)&hlo;
                *(unsigned*)&Dsm[(rlo+8)*132 + col] = *(unsigned*)&hhi;
            }
        }
    }
    asm volatile("cp.async.wait_all;" ::: "memory");
    __syncthreads();

    // ---- epilogue: D + bias + P1[i] + P2[idx]; stats; fp16 store ----
    float4 bb0 = *(const float4*)&bias[tx*4];
    float4 bb1 = *(const float4*)&bias[64 + tx*4];
    float bj[8] = {bb0.x,bb0.y,bb0.z,bb0.w,bb1.x,bb1.y,bb1.z,bb1.w};

    float s[8], ssq[8];
    #pragma unroll
    for(int c=0;c<8;c++){ s[c]=0.f; ssq[c]=0.f; }

    #pragma unroll
    for(int r=0;r<8;r++){
        int row = (r<4) ? (ty*4+r) : (64 + ty*4 + (r-4));
        int g = row0 + row;
        int irel = (g / Mm) - a0atom;
        uint2 da = *(const uint2*)&Dsm[row*132 + tx*4];
        uint2 db = *(const uint2*)&Dsm[row*132 + 64 + tx*4];
        uint2 ua = *(const uint2*)&sP1[irel*128 + tx*4];
        uint2 ub = *(const uint2*)&sP1[irel*128 + 64 + tx*4];
        uint2 va = *(const uint2*)&sP2[row*128 + tx*4];
        uint2 vb = *(const uint2*)&sP2[row*128 + 64 + tx*4];
        float2 d0 = __half22float2(*(__half2*)&da.x);
        float2 d1 = __half22float2(*(__half2*)&da.y);
        float2 d2 = __half22float2(*(__half2*)&db.x);
        float2 d3 = __half22float2(*(__half2*)&db.y);
        float2 p1a = __half22float2(*(__half2*)&ua.x);
        float2 p1b = __half22float2(*(__half2*)&ua.y);
        float2 p1c = __half22float2(*(__half2*)&ub.x);
        float2 p1d = __half22float2(*(__half2*)&ub.y);
        float2 p2a = __half22float2(*(__half2*)&va.x);
        float2 p2b = __half22float2(*(__half2*)&va.y);
        float2 p2c = __half22float2(*(__half2*)&vb.x);
        float2 p2d = __half22float2(*(__half2*)&vb.y);
        float am[8] = {d0.x,d0.y,d1.x,d1.y,d2.x,d2.y,d3.x,d3.y};
        float pv[8] = {p1a.x+p2a.x, p1a.y+p2a.y, p1b.x+p2b.x, p1b.y+p2b.y,
                       p1c.x+p2c.x, p1c.y+p2c.y, p1d.x+p2d.x, p1d.y+p2d.y};
        float out[8];
        #pragma unroll
        for(int c=0;c<8;c++){
            float v = am[c] + bj[c] + pv[c];
            out[c] = v; s[c] += v; ssq[c] += v*v;
        }
        __half2 h0 = __floats2half2_rn(out[0], out[1]);
        __half2 h1 = __floats2half2_rn(out[2], out[3]);
        __half2 h2v = __floats2half2_rn(out[4], out[5]);
        __half2 h3 = __floats2half2_rn(out[6], out[7]);
        __half* dst = g_gatedh + (size_t)g*128;
        *(uint2*)&dst[tx*4]    = make_uint2(*(unsigned*)&h0, *(unsigned*)&h1);
        *(uint2*)&dst[64+tx*4] = make_uint2(*(unsigned*)&h2v, *(unsigned*)&h3);
    }
    #pragma unroll
    for(int c=0;c<8;c++){
        int col = (c<4) ? (tx*4+c) : (64 + tx*4 + (c-4));
        atomicAdd(&reds [col], s[c]);
        atomicAdd(&redss[col], ssq[c]);
    }
    __syncthreads();
    if(tid < 128){
        atomicAdd(&g_stats1[tid],       (double)reds[tid]);
        atomicAdd(&g_stats1[128 + tid], (double)redss[tid]);
    }
}

__global__ void k_fin1(const float* __restrict__ g1, const float* __restrict__ be1){
    int j = threadIdx.x;                      // 128
    double n = (double)NM;
    double mu = g_stats1[j] / n;
    double var = g_stats1[128 + j] / n - mu*mu;
    float r = rsqrtf((float)var + 1e-5f);
    float sc = g1[j] * r;
    g_sc1[j] = sc;
    g_sh1[j] = be1[j] - (float)mu * sc;
}

// ------- BN1 apply + sigmoid*softplus + sum over M + BN2 stats (fp16 in) ----
__global__ void k_B(){
    __shared__ float rs[64], rss[64];
    int tid = threadIdx.x;                    // 256; 32 atoms/block
    int fg = (tid & 15) * 4;
    int s  = tid >> 4;                        // 0..15, 2 atoms each
    int base = blockIdx.x * 32 + s*2;
    if(tid < 64){ rs[tid] = 0.f; rss[tid] = 0.f; }
    float4 scf = *(const float4*)&g_sc1[fg];
    float4 shf = *(const float4*)&g_sh1[fg];
    float4 scc = *(const float4*)&g_sc1[64+fg];
    float4 shc = *(const float4*)&g_sh1[64+fg];
    float sc_f[4] = {scf.x,scf.y,scf.z,scf.w};
    float sh_f[4] = {shf.x,shf.y,shf.z,shf.w};
    float sc_c[4] = {scc.x,scc.y,scc.z,scc.w};
    float sh_c[4] = {shc.x,shc.y,shc.z,shc.w};
    __syncthreads();

    float ts[4] = {0,0,0,0}, tss[4] = {0,0,0,0};
    #pragma unroll
    for(int a = 0; a < 2; a++){
        int i = base + a;
        const __half* gp = g_gatedh + (size_t)i*Mm*F2;
        float acc[4] = {0,0,0,0};
        #pragma unroll
        for(int m = 0; m < Mm; m++){
            uint2 uf = *(const uint2*)&gp[m*F2 + fg];
            uint2 uc = *(const uint2*)&gp[m*F2 + 64 + fg];
            float2 f01 = __half22float2(*(__half2*)&uf.x);
            float2 f23 = __half22float2(*(__half2*)&uf.y);
            float2 c01 = __half22float2(*(__half2*)&uc.x);
            float2 c23 = __half22float2(*(__half2*)&uc.y);
            float f0[4] = {f01.x, f01.y, f23.x, f23.y};
            float c0[4] = {c01.x, c01.y, c23.x, c23.y};
            #pragma unroll
            for(int c=0;c<4;c++)
                acc[c] += sg(f0[c]*sc_f[c]+sh_f[c]) * sp(c0[c]*sc_c[c]+sh_c[c]);
        }
        *(float4*)&g_summed[i*64 + fg] = make_float4(acc[0],acc[1],acc[2],acc[3]);
        #pragma unroll
        for(int c=0;c<4;c++){ ts[c] += acc[c]; tss[c] += acc[c]*acc[c]; }
    }
    #pragma unroll
    for(int c=0;c<4;c++){
        atomicAdd(&rs [fg+c], ts[c]);
        atomicAdd(&rss[fg+c], tss[c]);
    }
    __syncthreads();
    if(tid < 64){
        atomicAdd(&g_stats2[tid],      (double)rs[tid]);
        atomicAdd(&g_stats2[64 + tid], (double)rss[tid]);
    }
}

__global__ void k_fin2(const float* __restrict__ g2, const float* __restrict__ be2){
    int j = threadIdx.x;                      // 64
    double n = (double)Nn;
    double mu = g_stats2[j] / n;
    double var = g_stats2[64 + j] / n - mu*mu;
    float r = rsqrtf((float)var + 1e-5f);
    float sc = g2[j] * r;
    g_sc2[j] = sc;
    g_sh2[j] = be2[j] - (float)mu * sc;
}

__global__ void k_upd(){
    int id = blockIdx.x*256 + threadIdx.x;    // N*16 threads (float4 each)
    int fg = (id & 15) * 4;
    float4 xv = *(const float4*)&g_x[id*4];
    float4 sv = *(const float4*)&g_summed[id*4];
    float4 sc = *(const float4*)&g_sc2[fg];
    float4 sh = *(const float4*)&g_sh2[fg];
    float4 o;
    o.x = sp(xv.x + sv.x*sc.x + sh.x);
    o.y = sp(xv.y + sv.y*sc.y + sh.y);
    o.z = sp(xv.z + sv.z*sc.z + sh.z);
    o.w = sp(xv.w + sv.w*sc.w + sh.w);
    *(float4*)&g_x[id*4] = o;
}

// ---------------- pooling + head ----------------
__global__ void k_pool_zero(){
    int id = blockIdx.x*256 + threadIdx.x;
    if(id < NCc*Ff) g_crys[id] = 0.f;
    else if(id < NCc*Ff + NCc) g_cnt[id - NCc*Ff] = 0.f;
}

__global__ void k_pool(const int* __restrict__ cidx){
    int id = blockIdx.x*256 + threadIdx.x;    // N*64 threads
    int i = id >> 6, f = id & 63;
    int c = cidx[i];
    atomicAdd(&g_crys[c*64 + f], g_x[id]);
    if(f == 0) atomicAdd(&g_cnt[c], 1.f);
}

__global__ void k_head(const float* __restrict__ W_fc, const float* __restrict__ b_fc,
                       const float* __restrict__ W_out, const float* __restrict__ b_out,
                       float* __restrict__ out){
    __shared__ float t[64];
    __shared__ float hred[128];
    int c = blockIdx.x, th = threadIdx.x;     // 128
    if(th < 64){
        float cn = fmaxf(g_cnt[c], 1.f);
        t[th] = sp(g_crys[c*64 + th] / cn);
    }
    __syncthreads();
    float acc = b_fc[th];
    #pragma unroll 4
    for(int f = 0; f < 64; f++) acc += t[f] * W_fc[f*128 + th];
    hred[th] = sp(acc) * W_out[th];
    __syncthreads();
    for(int o = 64; o > 0; o >>= 1){
        if(th < o) hred[th] += hred[th + o];
        __syncthreads();
    }
    if(th == 0) out[c] = hred[0] + b_out[0];
}

// ---------------- launcher ----------------
extern "C" void kernel_launch(void* const* d_in, const int* in_sizes, int n_in,
                              void* d_out, int out_size){
    const float* atom_fea = (const float*)d_in[0];
    const float* nbr_fea  = (const float*)d_in[1];
    const int*   nbr_idx  = (const int*)  d_in[2];
    const int*   cidx     = (const int*)  d_in[3];
    const float* W_emb    = (const float*)d_in[4];
    const float* b_emb    = (const float*)d_in[5];
    const float* W_full   = (const float*)d_in[6];
    const float* b_full   = (const float*)d_in[7];
    const float* g1       = (const float*)d_in[8];
    const float* be1      = (const float*)d_in[9];
    const float* g2       = (const float*)d_in[10];
    const float* be2      = (const float*)d_in[11];
    const float* W_fc     = (const float*)d_in[12];
    const float* b_fc     = (const float*)d_in[13];
    const float* W_out    = (const float*)d_in[14];
    const float* b_out    = (const float*)d_in[15];
    float* out = (float*)d_out;

    cudaFuncSetAttribute(k_Q, cudaFuncAttributeMaxDynamicSharedMemorySize, SMEMQ);

    k_emb<<<Nn/8, 512>>>(atom_fea, W_emb, b_emb);

    for(int l = 0; l < 3; l++){
        k_zero_stats<<<1, 256>>>();
        dim3 gp((Nn + 127)/128, 2);
        k_P<<<gp, 256>>>(W_full + (size_t)l*169*128);
        k_Q<<<NM/128, 256, SMEMQ>>>(nbr_fea, nbr_idx,
                                    W_full + (size_t)l*169*128, b_full + l*128);
        k_fin1<<<1, 128>>>(g1 + l*128, be1 + l*128);
        k_B<<<Nn/32, 256>>>();
        k_fin2<<<1, 64>>>(g2 + l*64, be2 + l*64);
        k_upd<<<(Nn*16)/256, 256>>>();
    }

    k_pool_zero<<<(NCc*Ff + NCc + 255)/256, 256>>>();
    k_pool<<<(Nn*Ff)/256, 256>>>(cidx);
    k_head<<<NCc, 128>>>(W_fc, b_fc, W_out, b_out, out);
}

// round 11
// speedup vs baseline: 1.5700x; 1.1733x over previous
#include <cuda_runtime.h>
#include <cuda_fp16.h>
#include <math.h>

#define Nn 60000
#define Mm 12
#define F0k 92
#define FBk 41
#define Ff 64
#define Hh 128
#define NCc 2000
#define F2 128
#define NM (Nn*Mm)

typedef unsigned long long u64;

// ---------------- helpers ----------------
__device__ __forceinline__ u64 ffma2(u64 a, u64 b, u64 c){
    u64 d;
    asm("fma.rn.f32x2 %0, %1, %2, %3;" : "=l"(d) : "l"(a), "l"(b), "l"(c));
    return d;
}
__device__ __forceinline__ u64 dup2(float x){
    u64 d; unsigned xi = __float_as_uint(x);
    asm("mov.b64 %0, {%1, %1};" : "=l"(d) : "r"(xi));
    return d;
}
__device__ __forceinline__ float2 unpk(u64 v){
    unsigned lo, hi;
    asm("mov.b64 {%0, %1}, %2;" : "=r"(lo), "=r"(hi) : "l"(v));
    return make_float2(__uint_as_float(lo), __uint_as_float(hi));
}
__device__ __forceinline__ void cpa16(unsigned dst, const void* src){
    asm volatile("cp.async.ca.shared.global [%0], [%1], 16;" :: "r"(dst), "l"(src) : "memory");
}
__device__ __forceinline__ void ldmx4(unsigned& r0, unsigned& r1, unsigned& r2,
                                      unsigned& r3, unsigned addr){
    asm volatile("ldmatrix.sync.aligned.m8n8.x4.shared.b16 {%0,%1,%2,%3}, [%4];"
                 : "=r"(r0), "=r"(r1), "=r"(r2), "=r"(r3) : "r"(addr));
}
__device__ __forceinline__ void hmma(float* d, const unsigned* a,
                                     unsigned b0, unsigned b1){
    asm volatile(
        "mma.sync.aligned.m16n8k16.row.col.f32.f16.f16.f32 "
        "{%0,%1,%2,%3}, {%4,%5,%6,%7}, {%8,%9}, {%0,%1,%2,%3};"
        : "+f"(d[0]), "+f"(d[1]), "+f"(d[2]), "+f"(d[3])
        : "r"(a[0]), "r"(a[1]), "r"(a[2]), "r"(a[3]), "r"(b0), "r"(b1));
}
#define SWZ(o) ((o) ^ (((o) >> 3) & 0x70))

// ---------------- scratch ----------------
__device__ float g_x[Nn*Ff];
__device__ __half g_Ph[Nn*256];                    // fp16 [P1|P2] per atom
__device__ __half g_nbrh[(size_t)NM*64];           // pre-swizzled A tiles (92MB)
__device__ __half g_Bh[8192];                      // pre-swizzled B tile (per layer)
__device__ __half g_gatedh[(size_t)NM*F2];
__device__ float g_summed[Nn*Ff];
__device__ double g_stats1[2*F2];
__device__ double g_stats2[2*Ff];
__device__ float g_sc1[F2], g_sh1[F2];
__device__ float g_sc2[Ff], g_sh2[Ff];
__device__ float g_crys[NCc*Ff];
__device__ float g_cnt[NCc];

__device__ __forceinline__ float sp(float x){
    return fmaxf(x, 0.f) + __logf(1.f + __expf(-fabsf(x)));
}
__device__ __forceinline__ float sg(float x){
    return __fdividef(1.f, 1.f + __expf(-x));
}

// ---------------- embedding ----------------
__global__ void k_emb(const float* __restrict__ af, const float* __restrict__ W,
                      const float* __restrict__ b){
    __shared__ float s_af[8][F0k];
    int base = blockIdx.x * 8;
    int tid = threadIdx.x;                    // 512
    for(int idx = tid; idx < 8*F0k; idx += 512){
        int a = idx / F0k, k = idx % F0k;
        s_af[a][k] = af[(base+a)*F0k + k];
    }
    __syncthreads();
    int a = tid >> 6, f = tid & 63;
    float acc = b[f];
    #pragma unroll 4
    for(int k = 0; k < F0k; k++) acc += s_af[a][k] * W[k*Ff + f];
    g_x[(base+a)*Ff + f] = acc;
}

__global__ void k_zero_stats(){
    int t = threadIdx.x;
    g_stats1[t] = 0.0;
    if(t < 2*Ff) g_stats2[t] = 0.0;
}

// ---- one-time: nbr_fea -> pre-swizzled fp16 A tiles (zero-padded K=64) ----
__global__ void k_prep(const float* __restrict__ nbr){
    __shared__ __align__(16) __half tile[8192];   // 16KB
    int tid = threadIdx.x;                        // 256
    int row0 = blockIdx.x * 128;
    for(int i = tid; i < 1024; i += 256)
        ((float4*)tile)[i] = make_float4(0.f,0.f,0.f,0.f);
    __syncthreads();
    for(int i2 = tid; i2 < 128*41; i2 += 256){
        int r = i2 / 41, k = i2 % 41;
        tile[SWZ((unsigned)(r*128 + k*2)) >> 1] =
            __float2half_rn(nbr[(size_t)(row0 + r)*41 + k]);
    }
    __syncthreads();
    float4* dst = (float4*)((char*)g_nbrh + (size_t)blockIdx.x*16384);
    for(int i = tid; i < 1024; i += 256) dst[i] = ((float4*)tile)[i];
}

// ---- per-layer: W3^T -> pre-swizzled fp16 B tile ----
__global__ void k_prepB(const float* __restrict__ Wf){
    const float* W3 = Wf + 128*128;
    int tid = threadIdx.x;                        // 256
    for(int i = tid; i < 4096; i += 256) ((unsigned*)g_Bh)[i] = 0u;
    __syncthreads();
    for(int i2 = tid; i2 < 41*128; i2 += 256){
        int k = i2 >> 7, n = i2 & 127;
        g_Bh[SWZ((unsigned)(n*128 + k*2)) >> 1] = __float2half_rn(W3[k*128 + n]);
    }
}

// ------ P = x @ [W1 | W2] (128x128 tile, 256 thr, 8x8, f32x2), fp16 out ----
__global__ void __launch_bounds__(256,2) k_P(const float* __restrict__ Wf){
    __shared__ __align__(16) float Ws[32][128];
    __shared__ __align__(16) float Xt[32][132];
    int hf = blockIdx.y;
    int base = blockIdx.x * 128;
    int rem  = Nn - base;
    int tid  = threadIdx.x;                   // 256
    int tx = tid & 15, ty = tid >> 4;

    u64 acc2[8][4];
    #pragma unroll
    for(int r=0;r<8;r++)
        #pragma unroll
        for(int c=0;c<4;c++) acc2[r][c]=0ULL;

    for(int kc = 0; kc < 2; kc++){
        for(int i2 = tid; i2 < 32*128; i2 += 256){
            int kk = i2 >> 7, j = i2 & 127;
            Ws[kk][j] = Wf[(hf*64 + kc*32 + kk)*128 + j];
        }
        for(int i2 = tid; i2 < 32*128; i2 += 256){
            int a = i2 >> 5, kk = i2 & 31;
            int atom = base + a; if(atom >= Nn) atom = Nn-1;
            Xt[kk][a] = g_x[atom*64 + kc*32 + kk];
        }
        __syncthreads();
        #pragma unroll 2
        for(int k = 0; k < 32; k++){
            float4 a0 = *(const float4*)&Xt[k][ty*4];
            float4 a1 = *(const float4*)&Xt[k][64 + ty*4];
            ulonglong2 w0 = *(const ulonglong2*)&Ws[k][tx*4];
            ulonglong2 w1 = *(const ulonglong2*)&Ws[k][64 + tx*4];
            u64 bp[4] = {w0.x, w0.y, w1.x, w1.y};
            float av[8] = {a0.x,a0.y,a0.z,a0.w,a1.x,a1.y,a1.z,a1.w};
            #pragma unroll
            for(int r=0;r<8;r++){
                u64 ad = dup2(av[r]);
                #pragma unroll
                for(int c=0;c<4;c++) acc2[r][c] = ffma2(ad, bp[c], acc2[r][c]);
            }
        }
        __syncthreads();
    }
    #pragma unroll
    for(int r=0;r<8;r++){
        int row = (r<4) ? (ty*4+r) : (64 + ty*4 + (r-4));
        if(row < rem){
            float2 v0 = unpk(acc2[r][0]), v1 = unpk(acc2[r][1]);
            float2 v2 = unpk(acc2[r][2]), v3 = unpk(acc2[r][3]);
            __half2 h0 = __floats2half2_rn(v0.x, v0.y);
            __half2 h1 = __floats2half2_rn(v1.x, v1.y);
            __half2 h2 = __floats2half2_rn(v2.x, v2.y);
            __half2 h3 = __floats2half2_rn(v3.x, v3.y);
            __half* dst = g_Ph + (size_t)(base+row)*256 + hf*128;
            *(uint2*)&dst[tx*4]    = make_uint2(*(unsigned*)&h0, *(unsigned*)&h1);
            *(uint2*)&dst[64+tx*4] = make_uint2(*(unsigned*)&h2, *(unsigned*)&h3);
        }
    }
}

// ---- k_Q dynamic smem layout (offsets from 1024-aligned base, bytes) ----
#define QOFF_A    0         // A tile: 128 x 64 fp16 (SW128) = 16384
#define QOFF_B    16384     // B tile: 128 x 64 fp16 (SW128) = 16384
                            // Dsm aliases [0, 33792): 128 x 132 fp16
#define QOFF_SP2  33792     // 128*128 fp16 = 32768
#define QOFF_SP1  66560     // 12*128 fp16 = 3072
#define QOFF_REDS 69632     // 128 f32
#define QOFF_RSS  70144     // 128 f32
#define SMEMQ     (70656 + 1024)

// -- edge GEMM (mma.sync f16) + P adds + bias + BN1 stats -------------------
__global__ void __launch_bounds__(256,2) k_Q(const int* __restrict__ idx,
                                             const float* __restrict__ bias){
    extern __shared__ __align__(16) char smraw[];
    unsigned sb0 = (unsigned)__cvta_generic_to_shared(smraw);
    unsigned sb  = (sb0 + 1023u) & ~1023u;
    char* smem = smraw + (sb - sb0);

    __half* Dsm = (__half*)(smem);                 // post-MMA alias of A|B
    __half* sP2 = (__half*)(smem + QOFF_SP2);
    __half* sP1 = (__half*)(smem + QOFF_SP1);
    float* reds = (float*)(smem + QOFF_REDS);
    float* redss= (float*)(smem + QOFF_RSS);

    int tid = threadIdx.x;                    // 256
    int wid = tid >> 5, lane = tid & 31;
    int row0 = blockIdx.x * 128;
    int tx = tid & 15, ty = tid >> 4;
    int a0atom = row0 / Mm;

    // ---- group 0: A tile (pre-swizzled) + B tile via cp.async ----
    {
        const char* srcA = (const char*)g_nbrh + (size_t)blockIdx.x*16384;
        const char* srcB = (const char*)g_Bh;
        #pragma unroll
        for(int c = 0; c < 4; c++){
            int ch = tid + c*256;
            cpa16(sb + QOFF_A + ch*16, srcA + ch*16);
            cpa16(sb + QOFF_B + ch*16, srcB + ch*16);
        }
    }
    asm volatile("cp.async.commit_group;" ::: "memory");

    // ---- group 1: P2 (gather) and P1 ----
    if(tid < 128){
        int nb = idx[row0 + tid];
        const __half* src = g_Ph + (size_t)nb*256 + 128;
        unsigned dst = sb + QOFF_SP2 + tid*256;
        #pragma unroll
        for(int c = 0; c < 16; c++) cpa16(dst + c*16, src + c*8);
    } else {
        int t2 = tid - 128;
        for(int j = t2; j < 192; j += 128){
            int at = j >> 4, c = j & 15;
            int atom = a0atom + at; if(atom >= Nn) atom = Nn-1;
            cpa16(sb + QOFF_SP1 + at*256 + c*16,
                  g_Ph + (size_t)atom*256 + c*8);
        }
    }
    asm volatile("cp.async.commit_group;" ::: "memory");

    if(tid < 128){ reds[tid] = 0.f; redss[tid] = 0.f; }
    asm volatile("cp.async.wait_group 1;" ::: "memory");
    __syncthreads();

    // ---- HMMA mainloop: warp tile 32 rows x 64 cols; K=48 in 3 steps ----
    int m0 = (wid & 3) * 32;
    int n0 = (wid >> 2) * 64;
    float acc[2][8][4];
    #pragma unroll
    for(int mt=0;mt<2;mt++)
        #pragma unroll
        for(int nt=0;nt<8;nt++)
            #pragma unroll
            for(int c=0;c<4;c++) acc[mt][nt][c]=0.f;

    int l7  = lane & 7;
    int aRowSel = (lane & 8) ? 8 : 0;
    int aColSel = (lane & 16) ? 8 : 0;
    int bRowSel = (lane & 16) ? 8 : 0;
    int bColSel = (lane & 8) ? 8 : 0;

    #pragma unroll
    for(int ks = 0; ks < 3; ks++){
        int k0 = ks*16;
        unsigned a[2][4];
        #pragma unroll
        for(int mt = 0; mt < 2; mt++){
            int r = m0 + mt*16 + l7 + aRowSel;
            unsigned addr = sb + QOFF_A + SWZ((unsigned)(r*128 + (k0 + aColSel)*2));
            ldmx4(a[mt][0], a[mt][1], a[mt][2], a[mt][3], addr);
        }
        #pragma unroll
        for(int ntp = 0; ntp < 4; ntp++){
            int n = n0 + ntp*16 + l7 + bRowSel;
            unsigned addr = sb + QOFF_B + SWZ((unsigned)(n*128 + (k0 + bColSel)*2));
            unsigned b0, b1, b2, b3;
            ldmx4(b0, b1, b2, b3, addr);
            hmma(acc[0][2*ntp],   a[0], b0, b1);
            hmma(acc[0][2*ntp+1], a[0], b2, b3);
            hmma(acc[1][2*ntp],   a[1], b0, b1);
            hmma(acc[1][2*ntp+1], a[1], b2, b3);
        }
    }
    __syncthreads();                          // A/B reads done; Dsm can alias

    // ---- stage D -> Dsm (fp16, 132-half padded rows) ----
    {
        int rl = lane >> 2, cq = (lane & 3)*2;
        #pragma unroll
        for(int mt = 0; mt < 2; mt++){
            int rlo = m0 + mt*16 + rl;
            #pragma unroll
            for(int nt = 0; nt < 8; nt++){
                int col = n0 + nt*8 + cq;
                __half2 hlo = __floats2half2_rn(acc[mt][nt][0], acc[mt][nt][1]);
                __half2 hhi = __floats2half2_rn(acc[mt][nt][2], acc[mt][nt][3]);
                *(unsigned*)&Dsm[rlo*132 + col]     = *(unsigned*)&hlo;
                *(unsigned*)&Dsm[(rlo+8)*132 + col] = *(unsigned*)&hhi;
            }
        }
    }
    asm volatile("cp.async.wait_group 0;" ::: "memory");
    __syncthreads();

    // ---- epilogue: D + bias + P1[i] + P2[idx]; stats; fp16 store ----
    float4 bb0 = *(const float4*)&bias[tx*4];
    float4 bb1 = *(const float4*)&bias[64 + tx*4];
    float bj[8] = {bb0.x,bb0.y,bb0.z,bb0.w,bb1.x,bb1.y,bb1.z,bb1.w};
    int rm0 = row0 - a0atom*Mm;

    float s[8], ssq[8];
    #pragma unroll
    for(int c=0;c<8;c++){ s[c]=0.f; ssq[c]=0.f; }

    #pragma unroll
    for(int r=0;r<8;r++){
        int row = (r<4) ? (ty*4+r) : (64 + ty*4 + (r-4));
        int g = row0 + row;
        int irel = (rm0 + row) / Mm;
        uint2 da = *(const uint2*)&Dsm[row*132 + tx*4];
        uint2 db = *(const uint2*)&Dsm[row*132 + 64 + tx*4];
        uint2 ua = *(const uint2*)&sP1[irel*128 + tx*4];
        uint2 ub = *(const uint2*)&sP1[irel*128 + 64 + tx*4];
        uint2 va = *(const uint2*)&sP2[row*128 + tx*4];
        uint2 vb = *(const uint2*)&sP2[row*128 + 64 + tx*4];
        float2 d0 = __half22float2(*(__half2*)&da.x);
        float2 d1 = __half22float2(*(__half2*)&da.y);
        float2 d2 = __half22float2(*(__half2*)&db.x);
        float2 d3 = __half22float2(*(__half2*)&db.y);
        float2 p1a = __half22float2(*(__half2*)&ua.x);
        float2 p1b = __half22float2(*(__half2*)&ua.y);
        float2 p1c = __half22float2(*(__half2*)&ub.x);
        float2 p1d = __half22float2(*(__half2*)&ub.y);
        float2 p2a = __half22float2(*(__half2*)&va.x);
        float2 p2b = __half22float2(*(__half2*)&va.y);
        float2 p2c = __half22float2(*(__half2*)&vb.x);
        float2 p2d = __half22float2(*(__half2*)&vb.y);
        float am[8] = {d0.x,d0.y,d1.x,d1.y,d2.x,d2.y,d3.x,d3.y};
        float pv[8] = {p1a.x+p2a.x, p1a.y+p2a.y, p1b.x+p2b.x, p1b.y+p2b.y,
                       p1c.x+p2c.x, p1c.y+p2c.y, p1d.x+p2d.x, p1d.y+p2d.y};
        float out[8];
        #pragma unroll
        for(int c=0;c<8;c++){
            float v = am[c] + bj[c] + pv[c];
            out[c] = v; s[c] += v; ssq[c] += v*v;
        }
        __half2 h0 = __floats2half2_rn(out[0], out[1]);
        __half2 h1 = __floats2half2_rn(out[2], out[3]);
        __half2 h2v = __floats2half2_rn(out[4], out[5]);
        __half2 h3 = __floats2half2_rn(out[6], out[7]);
        __half* dst = g_gatedh + (size_t)g*128;
        *(uint2*)&dst[tx*4]    = make_uint2(*(unsigned*)&h0, *(unsigned*)&h1);
        *(uint2*)&dst[64+tx*4] = make_uint2(*(unsigned*)&h2v, *(unsigned*)&h3);
    }
    #pragma unroll
    for(int c=0;c<8;c++){
        int col = (c<4) ? (tx*4+c) : (64 + tx*4 + (c-4));
        atomicAdd(&reds [col], s[c]);
        atomicAdd(&redss[col], ssq[c]);
    }
    __syncthreads();
    if(tid < 128){
        atomicAdd(&g_stats1[tid],       (double)reds[tid]);
        atomicAdd(&g_stats1[128 + tid], (double)redss[tid]);
    }
}

__global__ void k_fin1(const float* __restrict__ g1, const float* __restrict__ be1){
    int j = threadIdx.x;                      // 128
    double n = (double)NM;
    double mu = g_stats1[j] / n;
    double var = g_stats1[128 + j] / n - mu*mu;
    float r = rsqrtf((float)var + 1e-5f);
    float sc = g1[j] * r;
    g_sc1[j] = sc;
    g_sh1[j] = be1[j] - (float)mu * sc;
}

// ------- BN1 apply + sigmoid*softplus + sum over M + BN2 stats (fp16 in) ----
__global__ void k_B(){
    __shared__ float rs[64], rss[64];
    int tid = threadIdx.x;                    // 256; 32 atoms/block
    int fg = (tid & 15) * 4;
    int s  = tid >> 4;                        // 0..15, 2 atoms each
    int base = blockIdx.x * 32 + s*2;
    if(tid < 64){ rs[tid] = 0.f; rss[tid] = 0.f; }
    float4 scf = *(const float4*)&g_sc1[fg];
    float4 shf = *(const float4*)&g_sh1[fg];
    float4 scc = *(const float4*)&g_sc1[64+fg];
    float4 shc = *(const float4*)&g_sh1[64+fg];
    float sc_f[4] = {scf.x,scf.y,scf.z,scf.w};
    float sh_f[4] = {shf.x,shf.y,shf.z,shf.w};
    float sc_c[4] = {scc.x,scc.y,scc.z,scc.w};
    float sh_c[4] = {shc.x,shc.y,shc.z,shc.w};
    __syncthreads();

    float ts[4] = {0,0,0,0}, tss[4] = {0,0,0,0};
    #pragma unroll
    for(int a = 0; a < 2; a++){
        int i = base + a;
        const __half* gp = g_gatedh + (size_t)i*Mm*F2;
        float acc[4] = {0,0,0,0};
        #pragma unroll
        for(int m = 0; m < Mm; m++){
            uint2 uf = *(const uint2*)&gp[m*F2 + fg];
            uint2 uc = *(const uint2*)&gp[m*F2 + 64 + fg];
            float2 f01 = __half22float2(*(__half2*)&uf.x);
            float2 f23 = __half22float2(*(__half2*)&uf.y);
            float2 c01 = __half22float2(*(__half2*)&uc.x);
            float2 c23 = __half22float2(*(__half2*)&uc.y);
            float f0[4] = {f01.x, f01.y, f23.x, f23.y};
            float c0[4] = {c01.x, c01.y, c23.x, c23.y};
            #pragma unroll
            for(int c=0;c<4;c++)
                acc[c] += sg(f0[c]*sc_f[c]+sh_f[c]) * sp(c0[c]*sc_c[c]+sh_c[c]);
        }
        *(float4*)&g_summed[i*64 + fg] = make_float4(acc[0],acc[1],acc[2],acc[3]);
        #pragma unroll
        for(int c=0;c<4;c++){ ts[c] += acc[c]; tss[c] += acc[c]*acc[c]; }
    }
    #pragma unroll
    for(int c=0;c<4;c++){
        atomicAdd(&rs [fg+c], ts[c]);
        atomicAdd(&rss[fg+c], tss[c]);
    }
    __syncthreads();
    if(tid < 64){
        atomicAdd(&g_stats2[tid],      (double)rs[tid]);
        atomicAdd(&g_stats2[64 + tid], (double)rss[tid]);
    }
}

__global__ void k_fin2(const float* __restrict__ g2, const float* __restrict__ be2){
    int j = threadIdx.x;                      // 64
    double n = (double)Nn;
    double mu = g_stats2[j] / n;
    double var = g_stats2[64 + j] / n - mu*mu;
    float r = rsqrtf((float)var + 1e-5f);
    float sc = g2[j] * r;
    g_sc2[j] = sc;
    g_sh2[j] = be2[j] - (float)mu * sc;
}

__global__ void k_upd(){
    int id = blockIdx.x*256 + threadIdx.x;    // N*16 threads (float4 each)
    int fg = (id & 15) * 4;
    float4 xv = *(const float4*)&g_x[id*4];
    float4 sv = *(const float4*)&g_summed[id*4];
    float4 sc = *(const float4*)&g_sc2[fg];
    float4 sh = *(const float4*)&g_sh2[fg];
    float4 o;
    o.x = sp(xv.x + sv.x*sc.x + sh.x);
    o.y = sp(xv.y + sv.y*sc.y + sh.y);
    o.z = sp(xv.z + sv.z*sc.z + sh.z);
    o.w = sp(xv.w + sv.w*sc.w + sh.w);
    *(float4*)&g_x[id*4] = o;
}

// ---------------- pooling + head ----------------
__global__ void k_pool_zero(){
    int id = blockIdx.x*256 + threadIdx.x;
    if(id < NCc*Ff) g_crys[id] = 0.f;
    else if(id < NCc*Ff + NCc) g_cnt[id - NCc*Ff] = 0.f;
}

__global__ void k_pool(const int* __restrict__ cidx){
    int id = blockIdx.x*256 + threadIdx.x;    // N*64 threads
    int i = id >> 6, f = id & 63;
    int c = cidx[i];
    atomicAdd(&g_crys[c*64 + f], g_x[id]);
    if(f == 0) atomicAdd(&g_cnt[c], 1.f);
}

__global__ void k_head(const float* __restrict__ W_fc, const float* __restrict__ b_fc,
                       const float* __restrict__ W_out, const float* __restrict__ b_out,
                       float* __restrict__ out){
    __shared__ float t[64];
    __shared__ float hred[128];
    int c = blockIdx.x, th = threadIdx.x;     // 128
    if(th < 64){
        float cn = fmaxf(g_cnt[c], 1.f);
        t[th] = sp(g_crys[c*64 + th] / cn);
    }
    __syncthreads();
    float acc = b_fc[th];
    #pragma unroll 4
    for(int f = 0; f < 64; f++) acc += t[f] * W_fc[f*128 + th];
    hred[th] = sp(acc) * W_out[th];
    __syncthreads();
    for(int o = 64; o > 0; o >>= 1){
        if(th < o) hred[th] += hred[th + o];
        __syncthreads();
    }
    if(th == 0) out[c] = hred[0] + b_out[0];
}

// ---------------- launcher ----------------
extern "C" void kernel_launch(void* const* d_in, const int* in_sizes, int n_in,
                              void* d_out, int out_size){
    const float* atom_fea = (const float*)d_in[0];
    const float* nbr_fea  = (const float*)d_in[1];
    const int*   nbr_idx  = (const int*)  d_in[2];
    const int*   cidx     = (const int*)  d_in[3];
    const float* W_emb    = (const float*)d_in[4];
    const float* b_emb    = (const float*)d_in[5];
    const float* W_full   = (const float*)d_in[6];
    const float* b_full   = (const float*)d_in[7];
    const float* g1       = (const float*)d_in[8];
    const float* be1      = (const float*)d_in[9];
    const float* g2       = (const float*)d_in[10];
    const float* be2      = (const float*)d_in[11];
    const float* W_fc     = (const float*)d_in[12];
    const float* b_fc     = (const float*)d_in[13];
    const float* W_out    = (const float*)d_in[14];
    const float* b_out    = (const float*)d_in[15];
    float* out = (float*)d_out;

    cudaFuncSetAttribute(k_Q, cudaFuncAttributeMaxDynamicSharedMemorySize, SMEMQ);

    k_emb<<<Nn/8, 512>>>(atom_fea, W_emb, b_emb);
    k_prep<<<NM/128, 256>>>(nbr_fea);

    for(int l = 0; l < 3; l++){
        k_zero_stats<<<1, 256>>>();
        k_prepB<<<1, 256>>>(W_full + (size_t)l*169*128);
        dim3 gp((Nn + 127)/128, 2);
        k_P<<<gp, 256>>>(W_full + (size_t)l*169*128);
        k_Q<<<NM/128, 256, SMEMQ>>>(nbr_idx, b_full + l*128);
        k_fin1<<<1, 128>>>(g1 + l*128, be1 + l*128);
        k_B<<<Nn/32, 256>>>();
        k_fin2<<<1, 64>>>(g2 + l*64, be2 + l*64);
        k_upd<<<(Nn*16)/256, 256>>>();
    }

    k_pool_zero<<<(NCc*Ff + NCc + 255)/256, 256>>>();
    k_pool<<<(Nn*Ff)/256, 256>>>(cidx);
    k_head<<<NCc, 128>>>(W_fc, b_fc, W_out, b_out, out);
}

// round 12
// speedup vs baseline: 1.7548x; 1.1177x over previous
#include <cuda_runtime.h>
#include <cuda_fp16.h>
#include <math.h>

#define Nn 60000
#define Mm 12
#define F0k 92
#define FBk 41
#define Ff 64
#define Hh 128
#define NCc 2000
#define F2 128
#define NM (Nn*Mm)
#define NTILE 469            // ceil(Nn/128)

typedef unsigned long long u64;

// ---------------- helpers ----------------
__device__ __forceinline__ void cpa16(unsigned dst, const void* src){
    asm volatile("cp.async.ca.shared.global [%0], [%1], 16;" :: "r"(dst), "l"(src) : "memory");
}
__device__ __forceinline__ void ldmx4(unsigned& r0, unsigned& r1, unsigned& r2,
                                      unsigned& r3, unsigned addr){
    asm volatile("ldmatrix.sync.aligned.m8n8.x4.shared.b16 {%0,%1,%2,%3}, [%4];"
                 : "=r"(r0), "=r"(r1), "=r"(r2), "=r"(r3) : "r"(addr));
}
__device__ __forceinline__ void hmma(float* d, const unsigned* a,
                                     unsigned b0, unsigned b1){
    asm volatile(
        "mma.sync.aligned.m16n8k16.row.col.f32.f16.f16.f32 "
        "{%0,%1,%2,%3}, {%4,%5,%6,%7}, {%8,%9}, {%0,%1,%2,%3};"
        : "+f"(d[0]), "+f"(d[1]), "+f"(d[2]), "+f"(d[3])
        : "r"(a[0]), "r"(a[1]), "r"(a[2]), "r"(a[3]), "r"(b0), "r"(b1));
}
#define SWZ(o) ((o) ^ (((o) >> 3) & 0x70))

// ---------------- scratch ----------------
__device__ float g_x[Nn*Ff];
__device__ __half g_xh[(size_t)NTILE*8192];        // pre-swizzled x tiles (fp16)
__device__ __half g_Ph[Nn*256];                    // fp16 [P1|P2] per atom
__device__ __half g_nbrh[(size_t)NM*64];           // pre-swizzled A tiles (92MB)
__device__ __half g_Ball[9*8192];                  // pre-swizzled W tiles: [l][W1,W2,W3]
__device__ __half g_gatedh[(size_t)NM*F2];
__device__ float g_summed[Nn*Ff];
__device__ double g_stats1[2*F2];
__device__ double g_stats2[2*Ff];
__device__ float g_sc1[F2], g_sh1[F2];
__device__ float g_sc2[Ff], g_sh2[Ff];
__device__ float g_crys[NCc*Ff];
__device__ float g_cnt[NCc];

__device__ __forceinline__ float sp(float x){
    return fmaxf(x, 0.f) + __logf(1.f + __expf(-fabsf(x)));
}
__device__ __forceinline__ float sg(float x){
    return __fdividef(1.f, 1.f + __expf(-x));
}

// ---------------- embedding ----------------
__global__ void k_emb(const float* __restrict__ af, const float* __restrict__ W,
                      const float* __restrict__ b){
    __shared__ float s_af[8][F0k];
    int base = blockIdx.x * 8;
    int tid = threadIdx.x;                    // 512
    for(int idx = tid; idx < 8*F0k; idx += 512){
        int a = idx / F0k, k = idx % F0k;
        s_af[a][k] = af[(base+a)*F0k + k];
    }
    __syncthreads();
    int a = tid >> 6, f = tid & 63;
    float acc = b[f];
    #pragma unroll 4
    for(int k = 0; k < F0k; k++) acc += s_af[a][k] * W[k*Ff + f];
    g_x[(base+a)*Ff + f] = acc;
}

__global__ void k_zero_stats(){
    int t = threadIdx.x;
    g_stats1[t] = 0.0;
    if(t < 2*Ff) g_stats2[t] = 0.0;
}

// ---- g_x -> pre-swizzled fp16 tiles (once after emb; k_upd maintains) ----
__global__ void k_x2h(){
    int id = blockIdx.x*256 + threadIdx.x;    // Nn*16
    int i = id >> 4, fg = (id & 15) * 4;
    float4 xv = *(const float4*)&g_x[i*64 + fg];
    __half2 h0 = __floats2half2_rn(xv.x, xv.y);
    __half2 h1 = __floats2half2_rn(xv.z, xv.w);
    int t = i >> 7, r = i & 127;
    unsigned off = SWZ((unsigned)(r*128 + fg*2));
    *(uint2*)((char*)g_xh + (size_t)t*16384 + off) =
        make_uint2(*(unsigned*)&h0, *(unsigned*)&h1);
}

// ---- one-time: nbr_fea -> pre-swizzled fp16 A tiles (zero-padded K=64) ----
__global__ void k_prep(const float* __restrict__ nbr){
    __shared__ __align__(16) __half tile[8192];   // 16KB
    int tid = threadIdx.x;                        // 256
    int row0 = blockIdx.x * 128;
    for(int i = tid; i < 1024; i += 256)
        ((float4*)tile)[i] = make_float4(0.f,0.f,0.f,0.f);
    __syncthreads();
    for(int i2 = tid; i2 < 128*41; i2 += 256){
        int r = i2 / 41, k = i2 % 41;
        tile[SWZ((unsigned)(r*128 + k*2)) >> 1] =
            __float2half_rn(nbr[(size_t)(row0 + r)*41 + k]);
    }
    __syncthreads();
    float4* dst = (float4*)((char*)g_nbrh + (size_t)blockIdx.x*16384);
    for(int i = tid; i < 1024; i += 256) dst[i] = ((float4*)tile)[i];
}

// ---- one-time: all weight tiles -> pre-swizzled fp16 B format ----
// blockIdx.x = l*3 + mat; mat 0=W1, 1=W2 (K=64), 2=W3 (K=41 zero-padded)
__global__ void k_prepW(const float* __restrict__ W_full){
    __shared__ __align__(16) __half tile[8192];
    int b = blockIdx.x;
    int l = b / 3, mat = b % 3;
    const float* Wf = W_full + (size_t)l*169*128;
    int tid = threadIdx.x;                        // 256
    for(int i = tid; i < 1024; i += 256)
        ((float4*)tile)[i] = make_float4(0.f,0.f,0.f,0.f);
    __syncthreads();
    if(mat < 2){
        for(int i2 = tid; i2 < 64*128; i2 += 256){
            int k = i2 >> 7, n = i2 & 127;
            tile[SWZ((unsigned)(n*128 + k*2)) >> 1] =
                __float2half_rn(Wf[(mat*64 + k)*128 + n]);
        }
    } else {
        for(int i2 = tid; i2 < 41*128; i2 += 256){
            int k = i2 >> 7, n = i2 & 127;
            tile[SWZ((unsigned)(n*128 + k*2)) >> 1] =
                __float2half_rn(Wf[(128 + k)*128 + n]);
        }
    }
    __syncthreads();
    float4* dst = (float4*)(g_Ball + (size_t)b*8192);
    for(int i = tid; i < 1024; i += 256) dst[i] = ((float4*)tile)[i];
}

// ------ P = x @ [W1 | W2] via HMMA; blockIdx.y = half (0=W1/P1, 1=W2/P2) ----
__global__ void __launch_bounds__(256,2) k_P(int l){
    __shared__ __align__(128) __half As[8192];
    __shared__ __align__(128) __half Bs[8192];
    unsigned sbA = (unsigned)__cvta_generic_to_shared(As);
    unsigned sbB = (unsigned)__cvta_generic_to_shared(Bs);
    int tid = threadIdx.x, wid = tid >> 5, lane = tid & 31;
    int base = blockIdx.x * 128;
    int hf = blockIdx.y;

    const char* srcA = (const char*)g_xh + (size_t)blockIdx.x*16384;
    const char* srcB = (const char*)(g_Ball + (size_t)(l*3 + hf)*8192);
    #pragma unroll
    for(int c = 0; c < 4; c++){
        int ch = tid + c*256;
        cpa16(sbA + ch*16, srcA + ch*16);
        cpa16(sbB + ch*16, srcB + ch*16);
    }
    asm volatile("cp.async.commit_group;" ::: "memory");
    asm volatile("cp.async.wait_group 0;" ::: "memory");
    __syncthreads();

    int m0 = (wid & 3) * 32;
    int n0 = (wid >> 2) * 64;
    float acc[2][8][4];
    #pragma unroll
    for(int mt=0;mt<2;mt++)
        #pragma unroll
        for(int nt=0;nt<8;nt++)
            #pragma unroll
            for(int c=0;c<4;c++) acc[mt][nt][c]=0.f;

    int l7  = lane & 7;
    int aRowSel = (lane & 8) ? 8 : 0;
    int aColSel = (lane & 16) ? 8 : 0;
    int bRowSel = (lane & 16) ? 8 : 0;
    int bColSel = (lane & 8) ? 8 : 0;

    #pragma unroll
    for(int ks = 0; ks < 4; ks++){
        int k0 = ks*16;
        unsigned a[2][4];
        #pragma unroll
        for(int mt = 0; mt < 2; mt++){
            int r = m0 + mt*16 + l7 + aRowSel;
            unsigned addr = sbA + SWZ((unsigned)(r*128 + (k0 + aColSel)*2));
            ldmx4(a[mt][0], a[mt][1], a[mt][2], a[mt][3], addr);
        }
        #pragma unroll
        for(int ntp = 0; ntp < 4; ntp++){
            int n = n0 + ntp*16 + l7 + bRowSel;
            unsigned addr = sbB + SWZ((unsigned)(n*128 + (k0 + bColSel)*2));
            unsigned b0, b1, b2, b3;
            ldmx4(b0, b1, b2, b3, addr);
            hmma(acc[0][2*ntp],   a[0], b0, b1);
            hmma(acc[0][2*ntp+1], a[0], b2, b3);
            hmma(acc[1][2*ntp],   a[1], b0, b1);
            hmma(acc[1][2*ntp+1], a[1], b2, b3);
        }
    }

    // direct fp16 write to g_Ph
    int rl = lane >> 2, cq = (lane & 3)*2;
    #pragma unroll
    for(int mt = 0; mt < 2; mt++){
        int row = m0 + mt*16 + rl;
        int atom0 = base + row, atom1 = atom0 + 8;
        #pragma unroll
        for(int nt = 0; nt < 8; nt++){
            int col = hf*128 + n0 + nt*8 + cq;
            __half2 hlo = __floats2half2_rn(acc[mt][nt][0], acc[mt][nt][1]);
            __half2 hhi = __floats2half2_rn(acc[mt][nt][2], acc[mt][nt][3]);
            if(atom0 < Nn) *(unsigned*)&g_Ph[(size_t)atom0*256 + col] = *(unsigned*)&hlo;
            if(atom1 < Nn) *(unsigned*)&g_Ph[(size_t)atom1*256 + col] = *(unsigned*)&hhi;
        }
    }
}

// ---- k_Q dynamic smem layout (offsets from 1024-aligned base, bytes) ----
#define QOFF_A    0         // A tile: 128 x 64 fp16 (SW128) = 16384
#define QOFF_B    16384     // B tile: 128 x 64 fp16 (SW128) = 16384
                            // Dsm aliases [0, 33792): 128 x 132 fp16
#define QOFF_SP2  33792     // 128*128 fp16 = 32768
#define QOFF_SP1  66560     // 12*128 fp16 = 3072
#define QOFF_REDS 69632     // 128 f32
#define QOFF_RSS  70144     // 128 f32
#define SMEMQ     (70656 + 1024)

// -- edge GEMM (mma.sync f16) + P adds + bias + BN1 stats -------------------
__global__ void __launch_bounds__(256,2) k_Q(const int* __restrict__ idx,
                                             const float* __restrict__ bias, int l){
    extern __shared__ __align__(16) char smraw[];
    unsigned sb0 = (unsigned)__cvta_generic_to_shared(smraw);
    unsigned sb  = (sb0 + 1023u) & ~1023u;
    char* smem = smraw + (sb - sb0);

    __half* Dsm = (__half*)(smem);                 // post-MMA alias of A|B
    __half* sP2 = (__half*)(smem + QOFF_SP2);
    __half* sP1 = (__half*)(smem + QOFF_SP1);
    float* reds = (float*)(smem + QOFF_REDS);
    float* redss= (float*)(smem + QOFF_RSS);

    int tid = threadIdx.x;                    // 256
    int wid = tid >> 5, lane = tid & 31;
    int row0 = blockIdx.x * 128;
    int tx = tid & 15, ty = tid >> 4;
    int a0atom = row0 / Mm;

    // ---- group 0: A tile (pre-swizzled) + B tile via cp.async ----
    {
        const char* srcA = (const char*)g_nbrh + (size_t)blockIdx.x*16384;
        const char* srcB = (const char*)(g_Ball + (size_t)(l*3 + 2)*8192);
        #pragma unroll
        for(int c = 0; c < 4; c++){
            int ch = tid + c*256;
            cpa16(sb + QOFF_A + ch*16, srcA + ch*16);
            cpa16(sb + QOFF_B + ch*16, srcB + ch*16);
        }
    }
    asm volatile("cp.async.commit_group;" ::: "memory");

    // ---- group 1: P2 (gather) and P1 ----
    if(tid < 128){
        int nb = idx[row0 + tid];
        const __half* src = g_Ph + (size_t)nb*256 + 128;
        unsigned dst = sb + QOFF_SP2 + tid*256;
        #pragma unroll
        for(int c = 0; c < 16; c++) cpa16(dst + c*16, src + c*8);
    } else {
        int t2 = tid - 128;
        for(int j = t2; j < 192; j += 128){
            int at = j >> 4, c = j & 15;
            int atom = a0atom + at; if(atom >= Nn) atom = Nn-1;
            cpa16(sb + QOFF_SP1 + at*256 + c*16,
                  g_Ph + (size_t)atom*256 + c*8);
        }
    }
    asm volatile("cp.async.commit_group;" ::: "memory");

    if(tid < 128){ reds[tid] = 0.f; redss[tid] = 0.f; }
    asm volatile("cp.async.wait_group 1;" ::: "memory");
    __syncthreads();

    // ---- HMMA mainloop: warp tile 32 rows x 64 cols; K=48 in 3 steps ----
    int m0 = (wid & 3) * 32;
    int n0 = (wid >> 2) * 64;
    float acc[2][8][4];
    #pragma unroll
    for(int mt=0;mt<2;mt++)
        #pragma unroll
        for(int nt=0;nt<8;nt++)
            #pragma unroll
            for(int c=0;c<4;c++) acc[mt][nt][c]=0.f;

    int l7  = lane & 7;
    int aRowSel = (lane & 8) ? 8 : 0;
    int aColSel = (lane & 16) ? 8 : 0;
    int bRowSel = (lane & 16) ? 8 : 0;
    int bColSel = (lane & 8) ? 8 : 0;

    #pragma unroll
    for(int ks = 0; ks < 3; ks++){
        int k0 = ks*16;
        unsigned a[2][4];
        #pragma unroll
        for(int mt = 0; mt < 2; mt++){
            int r = m0 + mt*16 + l7 + aRowSel;
            unsigned addr = sb + QOFF_A + SWZ((unsigned)(r*128 + (k0 + aColSel)*2));
            ldmx4(a[mt][0], a[mt][1], a[mt][2], a[mt][3], addr);
        }
        #pragma unroll
        for(int ntp = 0; ntp < 4; ntp++){
            int n = n0 + ntp*16 + l7 + bRowSel;
            unsigned addr = sb + QOFF_B + SWZ((unsigned)(n*128 + (k0 + bColSel)*2));
            unsigned b0, b1, b2, b3;
            ldmx4(b0, b1, b2, b3, addr);
            hmma(acc[0][2*ntp],   a[0], b0, b1);
            hmma(acc[0][2*ntp+1], a[0], b2, b3);
            hmma(acc[1][2*ntp],   a[1], b0, b1);
            hmma(acc[1][2*ntp+1], a[1], b2, b3);
        }
    }
    __syncthreads();                          // A/B reads done; Dsm can alias

    // ---- stage D -> Dsm (fp16, 132-half padded rows) ----
    {
        int rl = lane >> 2, cq = (lane & 3)*2;
        #pragma unroll
        for(int mt = 0; mt < 2; mt++){
            int rlo = m0 + mt*16 + rl;
            #pragma unroll
            for(int nt = 0; nt < 8; nt++){
                int col = n0 + nt*8 + cq;
                __half2 hlo = __floats2half2_rn(acc[mt][nt][0], acc[mt][nt][1]);
                __half2 hhi = __floats2half2_rn(acc[mt][nt][2], acc[mt][nt][3]);
                *(unsigned*)&Dsm[rlo*132 + col]     = *(unsigned*)&hlo;
                *(unsigned*)&Dsm[(rlo+8)*132 + col] = *(unsigned*)&hhi;
            }
        }
    }
    asm volatile("cp.async.wait_group 0;" ::: "memory");
    __syncthreads();

    // ---- epilogue: D + bias + P1[i] + P2[idx]; stats; fp16 store ----
    float4 bb0 = *(const float4*)&bias[tx*4];
    float4 bb1 = *(const float4*)&bias[64 + tx*4];
    float bj[8] = {bb0.x,bb0.y,bb0.z,bb0.w,bb1.x,bb1.y,bb1.z,bb1.w};
    int rm0 = row0 - a0atom*Mm;

    float s[8], ssq[8];
    #pragma unroll
    for(int c=0;c<8;c++){ s[c]=0.f; ssq[c]=0.f; }

    #pragma unroll
    for(int r=0;r<8;r++){
        int row = (r<4) ? (ty*4+r) : (64 + ty*4 + (r-4));
        int g = row0 + row;
        int irel = (rm0 + row) / Mm;
        uint2 da = *(const uint2*)&Dsm[row*132 + tx*4];
        uint2 db = *(const uint2*)&Dsm[row*132 + 64 + tx*4];
        uint2 ua = *(const uint2*)&sP1[irel*128 + tx*4];
        uint2 ub = *(const uint2*)&sP1[irel*128 + 64 + tx*4];
        uint2 va = *(const uint2*)&sP2[row*128 + tx*4];
        uint2 vb = *(const uint2*)&sP2[row*128 + 64 + tx*4];
        float2 d0 = __half22float2(*(__half2*)&da.x);
        float2 d1 = __half22float2(*(__half2*)&da.y);
        float2 d2 = __half22float2(*(__half2*)&db.x);
        float2 d3 = __half22float2(*(__half2*)&db.y);
        float2 p1a = __half22float2(*(__half2*)&ua.x);
        float2 p1b = __half22float2(*(__half2*)&ua.y);
        float2 p1c = __half22float2(*(__half2*)&ub.x);
        float2 p1d = __half22float2(*(__half2*)&ub.y);
        float2 p2a = __half22float2(*(__half2*)&va.x);
        float2 p2b = __half22float2(*(__half2*)&va.y);
        float2 p2c = __half22float2(*(__half2*)&vb.x);
        float2 p2d = __half22float2(*(__half2*)&vb.y);
        float am[8] = {d0.x,d0.y,d1.x,d1.y,d2.x,d2.y,d3.x,d3.y};
        float pv[8] = {p1a.x+p2a.x, p1a.y+p2a.y, p1b.x+p2b.x, p1b.y+p2b.y,
                       p1c.x+p2c.x, p1c.y+p2c.y, p1d.x+p2d.x, p1d.y+p2d.y};
        float out[8];
        #pragma unroll
        for(int c=0;c<8;c++){
            float v = am[c] + bj[c] + pv[c];
            out[c] = v; s[c] += v; ssq[c] += v*v;
        }
        __half2 h0 = __floats2half2_rn(out[0], out[1]);
        __half2 h1 = __floats2half2_rn(out[2], out[3]);
        __half2 h2v = __floats2half2_rn(out[4], out[5]);
        __half2 h3 = __floats2half2_rn(out[6], out[7]);
        __half* dst = g_gatedh + (size_t)g*128;
        *(uint2*)&dst[tx*4]    = make_uint2(*(unsigned*)&h0, *(unsigned*)&h1);
        *(uint2*)&dst[64+tx*4] = make_uint2(*(unsigned*)&h2v, *(unsigned*)&h3);
    }
    #pragma unroll
    for(int c=0;c<8;c++){
        int col = (c<4) ? (tx*4+c) : (64 + tx*4 + (c-4));
        atomicAdd(&reds [col], s[c]);
        atomicAdd(&redss[col], ssq[c]);
    }
    __syncthreads();
    if(tid < 128){
        atomicAdd(&g_stats1[tid],       (double)reds[tid]);
        atomicAdd(&g_stats1[128 + tid], (double)redss[tid]);
    }
}

__global__ void k_fin1(const float* __restrict__ g1, const float* __restrict__ be1){
    int j = threadIdx.x;                      // 128
    double n = (double)NM;
    double su = g_stats1[j], ssq = g_stats1[128 + j];
    g_stats1[j] = 0.0; g_stats1[128 + j] = 0.0;   // re-zero for next layer
    double mu = su / n;
    double var = ssq / n - mu*mu;
    float r = rsqrtf((float)var + 1e-5f);
    float sc = g1[j] * r;
    g_sc1[j] = sc;
    g_sh1[j] = be1[j] - (float)mu * sc;
}

// ------- BN1 apply + sigmoid*softplus + sum over M + BN2 stats (fp16 in) ----
__global__ void k_B(){
    __shared__ float rs[64], rss[64];
    int tid = threadIdx.x;                    // 256; 32 atoms/block
    int fg = (tid & 15) * 4;
    int s  = tid >> 4;                        // 0..15, 2 atoms each
    int base = blockIdx.x * 32 + s*2;
    if(tid < 64){ rs[tid] = 0.f; rss[tid] = 0.f; }
    float4 scf = *(const float4*)&g_sc1[fg];
    float4 shf = *(const float4*)&g_sh1[fg];
    float4 scc = *(const float4*)&g_sc1[64+fg];
    float4 shc = *(const float4*)&g_sh1[64+fg];
    float sc_f[4] = {scf.x,scf.y,scf.z,scf.w};
    float sh_f[4] = {shf.x,shf.y,shf.z,shf.w};
    float sc_c[4] = {scc.x,scc.y,scc.z,scc.w};
    float sh_c[4] = {shc.x,shc.y,shc.z,shc.w};
    __syncthreads();

    float ts[4] = {0,0,0,0}, tss[4] = {0,0,0,0};
    #pragma unroll
    for(int a = 0; a < 2; a++){
        int i = base + a;
        const __half* gp = g_gatedh + (size_t)i*Mm*F2;
        float acc[4] = {0,0,0,0};
        #pragma unroll
        for(int m = 0; m < Mm; m++){
            uint2 uf = *(const uint2*)&gp[m*F2 + fg];
            uint2 uc = *(const uint2*)&gp[m*F2 + 64 + fg];
            float2 f01 = __half22float2(*(__half2*)&uf.x);
            float2 f23 = __half22float2(*(__half2*)&uf.y);
            float2 c01 = __half22float2(*(__half2*)&uc.x);
            float2 c23 = __half22float2(*(__half2*)&uc.y);
            float f0[4] = {f01.x, f01.y, f23.x, f23.y};
            float c0[4] = {c01.x, c01.y, c23.x, c23.y};
            #pragma unroll
            for(int c=0;c<4;c++)
                acc[c] += sg(f0[c]*sc_f[c]+sh_f[c]) * sp(c0[c]*sc_c[c]+sh_c[c]);
        }
        *(float4*)&g_summed[i*64 + fg] = make_float4(acc[0],acc[1],acc[2],acc[3]);
        #pragma unroll
        for(int c=0;c<4;c++){ ts[c] += acc[c]; tss[c] += acc[c]*acc[c]; }
    }
    #pragma unroll
    for(int c=0;c<4;c++){
        atomicAdd(&rs [fg+c], ts[c]);
        atomicAdd(&rss[fg+c], tss[c]);
    }
    __syncthreads();
    if(tid < 64){
        atomicAdd(&g_stats2[tid],      (double)rs[tid]);
        atomicAdd(&g_stats2[64 + tid], (double)rss[tid]);
    }
}

__global__ void k_fin2(const float* __restrict__ g2, const float* __restrict__ be2){
    int j = threadIdx.x;                      // 64
    double n = (double)Nn;
    double su = g_stats2[j], ssq = g_stats2[64 + j];
    g_stats2[j] = 0.0; g_stats2[64 + j] = 0.0;
    double mu = su / n;
    double var = ssq / n - mu*mu;
    float r = rsqrtf((float)var + 1e-5f);
    float sc = g2[j] * r;
    g_sc2[j] = sc;
    g_sh2[j] = be2[j] - (float)mu * sc;
}

__global__ void k_upd(){
    int id = blockIdx.x*256 + threadIdx.x;    // N*16 threads (float4 each)
    int i = id >> 4, fg = (id & 15) * 4;
    float4 xv = *(const float4*)&g_x[id*4];
    float4 sv = *(const float4*)&g_summed[id*4];
    float4 sc = *(const float4*)&g_sc2[fg];
    float4 sh = *(const float4*)&g_sh2[fg];
    float4 o;
    o.x = sp(xv.x + sv.x*sc.x + sh.x);
    o.y = sp(xv.y + sv.y*sc.y + sh.y);
    o.z = sp(xv.z + sv.z*sc.z + sh.z);
    o.w = sp(xv.w + sv.w*sc.w + sh.w);
    *(float4*)&g_x[id*4] = o;
    // maintain swizzled fp16 mirror for k_P
    __half2 h0 = __floats2half2_rn(o.x, o.y);
    __half2 h1 = __floats2half2_rn(o.z, o.w);
    int t = i >> 7, r = i & 127;
    unsigned off = SWZ((unsigned)(r*128 + fg*2));
    *(uint2*)((char*)g_xh + (size_t)t*16384 + off) =
        make_uint2(*(unsigned*)&h0, *(unsigned*)&h1);
}

// ---------------- pooling + head ----------------
__global__ void k_pool_zero(){
    int id = blockIdx.x*256 + threadIdx.x;
    if(id < NCc*Ff) g_crys[id] = 0.f;
    else if(id < NCc*Ff + NCc) g_cnt[id - NCc*Ff] = 0.f;
}

__global__ void k_pool(const int* __restrict__ cidx){
    int id = blockIdx.x*256 + threadIdx.x;    // N*64 threads
    int i = id >> 6, f = id & 63;
    int c = cidx[i];
    atomicAdd(&g_crys[c*64 + f], g_x[id]);
    if(f == 0) atomicAdd(&g_cnt[c], 1.f);
}

__global__ void k_head(const float* __restrict__ W_fc, const float* __restrict__ b_fc,
                       const float* __restrict__ W_out, const float* __restrict__ b_out,
                       float* __restrict__ out){
    __shared__ float t[64];
    __shared__ float hred[128];
    int c = blockIdx.x, th = threadIdx.x;     // 128
    if(th < 64){
        float cn = fmaxf(g_cnt[c], 1.f);
        t[th] = sp(g_crys[c*64 + th] / cn);
    }
    __syncthreads();
    float acc = b_fc[th];
    #pragma unroll 4
    for(int f = 0; f < 64; f++) acc += t[f] * W_fc[f*128 + th];
    hred[th] = sp(acc) * W_out[th];
    __syncthreads();
    for(int o = 64; o > 0; o >>= 1){
        if(th < o) hred[th] += hred[th + o];
        __syncthreads();
    }
    if(th == 0) out[c] = hred[0] + b_out[0];
}

// ---------------- launcher ----------------
extern "C" void kernel_launch(void* const* d_in, const int* in_sizes, int n_in,
                              void* d_out, int out_size){
    const float* atom_fea = (const float*)d_in[0];
    const float* nbr_fea  = (const float*)d_in[1];
    const int*   nbr_idx  = (const int*)  d_in[2];
    const int*   cidx     = (const int*)  d_in[3];
    const float* W_emb    = (const float*)d_in[4];
    const float* b_emb    = (const float*)d_in[5];
    const float* W_full   = (const float*)d_in[6];
    const float* b_full   = (const float*)d_in[7];
    const float* g1       = (const float*)d_in[8];
    const float* be1      = (const float*)d_in[9];
    const float* g2       = (const float*)d_in[10];
    const float* be2      = (const float*)d_in[11];
    const float* W_fc     = (const float*)d_in[12];
    const float* b_fc     = (const float*)d_in[13];
    const float* W_out    = (const float*)d_in[14];
    const float* b_out    = (const float*)d_in[15];
    float* out = (float*)d_out;

    cudaFuncSetAttribute(k_Q, cudaFuncAttributeMaxDynamicSharedMemorySize, SMEMQ);

    k_emb<<<Nn/8, 512>>>(atom_fea, W_emb, b_emb);
    k_prep<<<NM/128, 256>>>(nbr_fea);
    k_prepW<<<9, 256>>>(W_full);
    k_x2h<<<(Nn*16)/256, 256>>>();
    k_zero_stats<<<1, 256>>>();

    for(int l = 0; l < 3; l++){
        dim3 gp(NTILE, 2);
        k_P<<<gp, 256>>>(l);
        k_Q<<<NM/128, 256, SMEMQ>>>(nbr_idx, b_full + l*128, l);
        k_fin1<<<1, 128>>>(g1 + l*128, be1 + l*128);
        k_B<<<Nn/32, 256>>>();
        k_fin2<<<1, 64>>>(g2 + l*64, be2 + l*64);
        k_upd<<<(Nn*16)/256, 256>>>();
    }

    k_pool_zero<<<(NCc*Ff + NCc + 255)/256, 256>>>();
    k_pool<<<(Nn*Ff)/256, 256>>>(cidx);
    k_head<<<NCc, 128>>>(W_fc, b_fc, W_out, b_out, out);
}

// round 13
// speedup vs baseline: 2.2502x; 1.2823x over previous
#include <cuda_runtime.h>
#include <cuda_fp16.h>
#include <math.h>

#define Nn 60000
#define Mm 12
#define F0k 92
#define FBk 41
#define Ff 64
#define Hh 128
#define NCc 2000
#define F2 128
#define NM (Nn*Mm)
#define NTILE 469            // ceil(Nn/128)

typedef unsigned long long u64;

// ---------------- helpers ----------------
__device__ __forceinline__ void cpa16(unsigned dst, const void* src){
    asm volatile("cp.async.ca.shared.global [%0], [%1], 16;" :: "r"(dst), "l"(src) : "memory");
}
__device__ __forceinline__ void ldmx4(unsigned& r0, unsigned& r1, unsigned& r2,
                                      unsigned& r3, unsigned addr){
    asm volatile("ldmatrix.sync.aligned.m8n8.x4.shared.b16 {%0,%1,%2,%3}, [%4];"
                 : "=r"(r0), "=r"(r1), "=r"(r2), "=r"(r3) : "r"(addr));
}
__device__ __forceinline__ void hmma(float* d, const unsigned* a,
                                     unsigned b0, unsigned b1){
    asm volatile(
        "mma.sync.aligned.m16n8k16.row.col.f32.f16.f16.f32 "
        "{%0,%1,%2,%3}, {%4,%5,%6,%7}, {%8,%9}, {%0,%1,%2,%3};"
        : "+f"(d[0]), "+f"(d[1]), "+f"(d[2]), "+f"(d[3])
        : "r"(a[0]), "r"(a[1]), "r"(a[2]), "r"(a[3]), "r"(b0), "r"(b1));
}
#define SWZ(o) ((o) ^ (((o) >> 3) & 0x70))

// ---------------- scratch ----------------
__device__ float g_x[Nn*Ff];
__device__ __half g_xh[(size_t)NTILE*8192];        // pre-swizzled x tiles (fp16)
__device__ __half g_Ph[Nn*256];                    // fp16 [P1|P2] per atom
__device__ __half g_nbrh[(size_t)NM*64];           // pre-swizzled A tiles (92MB)
__device__ __half g_Ball[9*8192];                  // pre-swizzled W tiles: [l][W1,W2,W3]
__device__ __half g_gatedh[(size_t)NM*F2];
__device__ float g_summed[Nn*Ff];
__device__ double g_stats1[2*F2];
__device__ double g_stats2[2*Ff];
__device__ float g_sc1[F2], g_sh1[F2];
__device__ float g_sc2[Ff], g_sh2[Ff];
__device__ float g_crys[NCc*Ff];
__device__ float g_cnt[NCc];

__device__ __forceinline__ float sp(float x){
    return fmaxf(x, 0.f) + __logf(1.f + __expf(-fabsf(x)));
}
__device__ __forceinline__ float sg(float x){
    return __fdividef(1.f, 1.f + __expf(-x));
}

// ---------------- embedding ----------------
__global__ void k_emb(const float* __restrict__ af, const float* __restrict__ W,
                      const float* __restrict__ b){
    __shared__ float s_af[8][F0k];
    int base = blockIdx.x * 8;
    int tid = threadIdx.x;                    // 512
    for(int idx = tid; idx < 8*F0k; idx += 512){
        int a = idx / F0k, k = idx % F0k;
        s_af[a][k] = af[(base+a)*F0k + k];
    }
    __syncthreads();
    int a = tid >> 6, f = tid & 63;
    float acc = b[f];
    #pragma unroll 4
    for(int k = 0; k < F0k; k++) acc += s_af[a][k] * W[k*Ff + f];
    g_x[(base+a)*Ff + f] = acc;
}

__global__ void k_zero_stats(){
    int t = threadIdx.x;
    g_stats1[t] = 0.0;
    if(t < 2*Ff) g_stats2[t] = 0.0;
}

// ---- g_x -> pre-swizzled fp16 tiles (once after emb; k_upd maintains) ----
__global__ void k_x2h(){
    int id = blockIdx.x*256 + threadIdx.x;    // Nn*16
    int i = id >> 4, fg = (id & 15) * 4;
    float4 xv = *(const float4*)&g_x[i*64 + fg];
    __half2 h0 = __floats2half2_rn(xv.x, xv.y);
    __half2 h1 = __floats2half2_rn(xv.z, xv.w);
    int t = i >> 7, r = i & 127;
    unsigned off = SWZ((unsigned)(r*128 + fg*2));
    *(uint2*)((char*)g_xh + (size_t)t*16384 + off) =
        make_uint2(*(unsigned*)&h0, *(unsigned*)&h1);
}

// ---- one-time: nbr_fea -> pre-swizzled fp16 A tiles (zero-padded K=64) ----
__global__ void k_prep(const float* __restrict__ nbr){
    __shared__ __align__(16) __half tile[8192];   // 16KB
    int tid = threadIdx.x;                        // 256
    int row0 = blockIdx.x * 128;
    for(int i = tid; i < 1024; i += 256)
        ((float4*)tile)[i] = make_float4(0.f,0.f,0.f,0.f);
    __syncthreads();
    for(int i2 = tid; i2 < 128*41; i2 += 256){
        int r = i2 / 41, k = i2 % 41;
        tile[SWZ((unsigned)(r*128 + k*2)) >> 1] =
            __float2half_rn(nbr[(size_t)(row0 + r)*41 + k]);
    }
    __syncthreads();
    float4* dst = (float4*)((char*)g_nbrh + (size_t)blockIdx.x*16384);
    for(int i = tid; i < 1024; i += 256) dst[i] = ((float4*)tile)[i];
}

// ---- one-time: all weight tiles -> pre-swizzled fp16 B format ----
__global__ void k_prepW(const float* __restrict__ W_full){
    __shared__ __align__(16) __half tile[8192];
    int b = blockIdx.x;
    int l = b / 3, mat = b % 3;
    const float* Wf = W_full + (size_t)l*169*128;
    int tid = threadIdx.x;                        // 256
    for(int i = tid; i < 1024; i += 256)
        ((float4*)tile)[i] = make_float4(0.f,0.f,0.f,0.f);
    __syncthreads();
    if(mat < 2){
        for(int i2 = tid; i2 < 64*128; i2 += 256){
            int k = i2 >> 7, n = i2 & 127;
            tile[SWZ((unsigned)(n*128 + k*2)) >> 1] =
                __float2half_rn(Wf[(mat*64 + k)*128 + n]);
        }
    } else {
        for(int i2 = tid; i2 < 41*128; i2 += 256){
            int k = i2 >> 7, n = i2 & 127;
            tile[SWZ((unsigned)(n*128 + k*2)) >> 1] =
                __float2half_rn(Wf[(128 + k)*128 + n]);
        }
    }
    __syncthreads();
    float4* dst = (float4*)(g_Ball + (size_t)b*8192);
    for(int i = tid; i < 1024; i += 256) dst[i] = ((float4*)tile)[i];
}

// ------ P = x @ [W1 | W2] via HMMA; blockIdx.y = half (0=W1/P1, 1=W2/P2) ----
__global__ void __launch_bounds__(256,2) k_P(int l){
    __shared__ __align__(128) __half As[8192];
    __shared__ __align__(128) __half Bs[8192];
    unsigned sbA = (unsigned)__cvta_generic_to_shared(As);
    unsigned sbB = (unsigned)__cvta_generic_to_shared(Bs);
    int tid = threadIdx.x, wid = tid >> 5, lane = tid & 31;
    int base = blockIdx.x * 128;
    int hf = blockIdx.y;

    const char* srcA = (const char*)g_xh + (size_t)blockIdx.x*16384;
    const char* srcB = (const char*)(g_Ball + (size_t)(l*3 + hf)*8192);
    #pragma unroll
    for(int c = 0; c < 4; c++){
        int ch = tid + c*256;
        cpa16(sbA + ch*16, srcA + ch*16);
        cpa16(sbB + ch*16, srcB + ch*16);
    }
    asm volatile("cp.async.commit_group;" ::: "memory");
    asm volatile("cp.async.wait_group 0;" ::: "memory");
    __syncthreads();

    int m0 = (wid & 3) * 32;
    int n0 = (wid >> 2) * 64;
    float acc[2][8][4];
    #pragma unroll
    for(int mt=0;mt<2;mt++)
        #pragma unroll
        for(int nt=0;nt<8;nt++)
            #pragma unroll
            for(int c=0;c<4;c++) acc[mt][nt][c]=0.f;

    int l7  = lane & 7;
    int aRowSel = (lane & 8) ? 8 : 0;
    int aColSel = (lane & 16) ? 8 : 0;
    int bRowSel = (lane & 16) ? 8 : 0;
    int bColSel = (lane & 8) ? 8 : 0;

    #pragma unroll
    for(int ks = 0; ks < 4; ks++){
        int k0 = ks*16;
        unsigned a[2][4];
        #pragma unroll
        for(int mt = 0; mt < 2; mt++){
            int r = m0 + mt*16 + l7 + aRowSel;
            unsigned addr = sbA + SWZ((unsigned)(r*128 + (k0 + aColSel)*2));
            ldmx4(a[mt][0], a[mt][1], a[mt][2], a[mt][3], addr);
        }
        #pragma unroll
        for(int ntp = 0; ntp < 4; ntp++){
            int n = n0 + ntp*16 + l7 + bRowSel;
            unsigned addr = sbB + SWZ((unsigned)(n*128 + (k0 + bColSel)*2));
            unsigned b0, b1, b2, b3;
            ldmx4(b0, b1, b2, b3, addr);
            hmma(acc[0][2*ntp],   a[0], b0, b1);
            hmma(acc[0][2*ntp+1], a[0], b2, b3);
            hmma(acc[1][2*ntp],   a[1], b0, b1);
            hmma(acc[1][2*ntp+1], a[1], b2, b3);
        }
    }

    // direct fp16 write to g_Ph
    int rl = lane >> 2, cq = (lane & 3)*2;
    #pragma unroll
    for(int mt = 0; mt < 2; mt++){
        int row = m0 + mt*16 + rl;
        int atom0 = base + row, atom1 = atom0 + 8;
        #pragma unroll
        for(int nt = 0; nt < 8; nt++){
            int col = hf*128 + n0 + nt*8 + cq;
            __half2 hlo = __floats2half2_rn(acc[mt][nt][0], acc[mt][nt][1]);
            __half2 hhi = __floats2half2_rn(acc[mt][nt][2], acc[mt][nt][3]);
            if(atom0 < Nn) *(unsigned*)&g_Ph[(size_t)atom0*256 + col] = *(unsigned*)&hlo;
            if(atom1 < Nn) *(unsigned*)&g_Ph[(size_t)atom1*256 + col] = *(unsigned*)&hhi;
        }
    }
}

// ---- k_Q dynamic smem layout (offsets from 1024-aligned base, bytes) ----
#define QOFF_A    0         // A tile: 128 x 64 fp16 (SW128) = 16384
#define QOFF_B    16384     // B tile: 128 x 64 fp16 (SW128) = 16384
                            // Dsm aliases [0, 34816): 128 x 136 fp16
#define QOFF_SP2  34816     // 128*128 fp16 = 32768; post-epilogue: stat partials
#define QOFF_SP1  67584     // 12*128 fp16 = 3072
#define SMEMQ     (70656 + 1024)
#define DPAD 136

// -- edge GEMM (mma.sync f16) + P adds + bias + BN1 stats -------------------
__global__ void __launch_bounds__(256,2) k_Q(const int* __restrict__ idx,
                                             const float* __restrict__ bias, int l){
    extern __shared__ __align__(16) char smraw[];
    unsigned sb0 = (unsigned)__cvta_generic_to_shared(smraw);
    unsigned sb  = (sb0 + 1023u) & ~1023u;
    char* smem = smraw + (sb - sb0);

    __half* Dsm = (__half*)(smem);                 // post-MMA alias of A|B (+SP2 head)
    __half* sP2 = (__half*)(smem + QOFF_SP2);
    __half* sP1 = (__half*)(smem + QOFF_SP1);

    int tid = threadIdx.x;                    // 256
    int wid = tid >> 5, lane = tid & 31;
    int row0 = blockIdx.x * 128;
    int tx = tid & 15, ty = tid >> 4;
    int a0atom = row0 / Mm;

    // ---- group 0: A tile (pre-swizzled) + B tile via cp.async ----
    {
        const char* srcA = (const char*)g_nbrh + (size_t)blockIdx.x*16384;
        const char* srcB = (const char*)(g_Ball + (size_t)(l*3 + 2)*8192);
        #pragma unroll
        for(int c = 0; c < 4; c++){
            int ch = tid + c*256;
            cpa16(sb + QOFF_A + ch*16, srcA + ch*16);
            cpa16(sb + QOFF_B + ch*16, srcB + ch*16);
        }
    }
    asm volatile("cp.async.commit_group;" ::: "memory");

    // ---- group 1: P2 (gather) and P1 ----
    if(tid < 128){
        int nb = idx[row0 + tid];
        const __half* src = g_Ph + (size_t)nb*256 + 128;
        unsigned dst = sb + QOFF_SP2 + tid*256;
        #pragma unroll
        for(int c = 0; c < 16; c++) cpa16(dst + c*16, src + c*8);
    } else {
        int t2 = tid - 128;
        for(int j = t2; j < 192; j += 128){
            int at = j >> 4, c = j & 15;
            int atom = a0atom + at; if(atom >= Nn) atom = Nn-1;
            cpa16(sb + QOFF_SP1 + at*256 + c*16,
                  g_Ph + (size_t)atom*256 + c*8);
        }
    }
    asm volatile("cp.async.commit_group;" ::: "memory");
    asm volatile("cp.async.wait_group 1;" ::: "memory");
    __syncthreads();

    // ---- HMMA mainloop: warp tile 32 rows x 64 cols; K=48 in 3 steps ----
    int m0 = (wid & 3) * 32;
    int n0 = (wid >> 2) * 64;
    float acc[2][8][4];
    #pragma unroll
    for(int mt=0;mt<2;mt++)
        #pragma unroll
        for(int nt=0;nt<8;nt++)
            #pragma unroll
            for(int c=0;c<4;c++) acc[mt][nt][c]=0.f;

    int l7  = lane & 7;
    int aRowSel = (lane & 8) ? 8 : 0;
    int aColSel = (lane & 16) ? 8 : 0;
    int bRowSel = (lane & 16) ? 8 : 0;
    int bColSel = (lane & 8) ? 8 : 0;

    #pragma unroll
    for(int ks = 0; ks < 3; ks++){
        int k0 = ks*16;
        unsigned a[2][4];
        #pragma unroll
        for(int mt = 0; mt < 2; mt++){
            int r = m0 + mt*16 + l7 + aRowSel;
            unsigned addr = sb + QOFF_A + SWZ((unsigned)(r*128 + (k0 + aColSel)*2));
            ldmx4(a[mt][0], a[mt][1], a[mt][2], a[mt][3], addr);
        }
        #pragma unroll
        for(int ntp = 0; ntp < 4; ntp++){
            int n = n0 + ntp*16 + l7 + bRowSel;
            unsigned addr = sb + QOFF_B + SWZ((unsigned)(n*128 + (k0 + bColSel)*2));
            unsigned b0, b1, b2, b3;
            ldmx4(b0, b1, b2, b3, addr);
            hmma(acc[0][2*ntp],   a[0], b0, b1);
            hmma(acc[0][2*ntp+1], a[0], b2, b3);
            hmma(acc[1][2*ntp],   a[1], b0, b1);
            hmma(acc[1][2*ntp+1], a[1], b2, b3);
        }
    }
    __syncthreads();                          // A/B reads done; Dsm can alias

    // ---- stage D -> Dsm (fp16, DPAD-half padded rows) ----
    {
        int rl = lane >> 2, cq = (lane & 3)*2;
        #pragma unroll
        for(int mt = 0; mt < 2; mt++){
            int rlo = m0 + mt*16 + rl;
            #pragma unroll
            for(int nt = 0; nt < 8; nt++){
                int col = n0 + nt*8 + cq;
                __half2 hlo = __floats2half2_rn(acc[mt][nt][0], acc[mt][nt][1]);
                __half2 hhi = __floats2half2_rn(acc[mt][nt][2], acc[mt][nt][3]);
                *(unsigned*)&Dsm[rlo*DPAD + col]     = *(unsigned*)&hlo;
                *(unsigned*)&Dsm[(rlo+8)*DPAD + col] = *(unsigned*)&hhi;
            }
        }
    }
    asm volatile("cp.async.wait_group 0;" ::: "memory");
    __syncthreads();

    // ---- epilogue: cols [tx*8, tx*8+8) per thread; 16B transactions ----
    float4 bbA = *(const float4*)&bias[tx*8];
    float4 bbB = *(const float4*)&bias[tx*8 + 4];
    float bj[8] = {bbA.x,bbA.y,bbA.z,bbA.w,bbB.x,bbB.y,bbB.z,bbB.w};
    int rm0 = row0 - a0atom*Mm;

    float s[8], ssq[8];
    #pragma unroll
    for(int c=0;c<8;c++){ s[c]=0.f; ssq[c]=0.f; }

    #pragma unroll
    for(int r=0;r<8;r++){
        int row = (r<4) ? (ty*4+r) : (64 + ty*4 + (r-4));
        int g = row0 + row;
        int irel = (rm0 + row) / Mm;
        uint4 dd = *(const uint4*)&Dsm[row*DPAD + tx*8];
        uint4 uu = *(const uint4*)&sP1[irel*128 + tx*8];
        uint4 vv = *(const uint4*)&sP2[row*128 + tx*8];
        float2 d0 = __half22float2(*(__half2*)&dd.x);
        float2 d1 = __half22float2(*(__half2*)&dd.y);
        float2 d2 = __half22float2(*(__half2*)&dd.z);
        float2 d3 = __half22float2(*(__half2*)&dd.w);
        float2 p0 = __half22float2(*(__half2*)&uu.x);
        float2 p1 = __half22float2(*(__half2*)&uu.y);
        float2 p2 = __half22float2(*(__half2*)&uu.z);
        float2 p3 = __half22float2(*(__half2*)&uu.w);
        float2 q0 = __half22float2(*(__half2*)&vv.x);
        float2 q1 = __half22float2(*(__half2*)&vv.y);
        float2 q2 = __half22float2(*(__half2*)&vv.z);
        float2 q3 = __half22float2(*(__half2*)&vv.w);
        float am[8] = {d0.x,d0.y,d1.x,d1.y,d2.x,d2.y,d3.x,d3.y};
        float pv[8] = {p0.x+q0.x, p0.y+q0.y, p1.x+q1.x, p1.y+q1.y,
                       p2.x+q2.x, p2.y+q2.y, p3.x+q3.x, p3.y+q3.y};
        float out[8];
        #pragma unroll
        for(int c=0;c<8;c++){
            float v = am[c] + bj[c] + pv[c];
            out[c] = v; s[c] += v; ssq[c] += v*v;
        }
        __half2 h0 = __floats2half2_rn(out[0], out[1]);
        __half2 h1 = __floats2half2_rn(out[2], out[3]);
        __half2 h2 = __floats2half2_rn(out[4], out[5]);
        __half2 h3 = __floats2half2_rn(out[6], out[7]);
        *(uint4*)&g_gatedh[(size_t)g*128 + tx*8] =
            make_uint4(*(unsigned*)&h0, *(unsigned*)&h1,
                       *(unsigned*)&h2, *(unsigned*)&h3);
    }

    // ---- BN1 stats: shuffle-reduce, warp partials in (free) sP2 region ----
    #pragma unroll
    for(int c=0;c<8;c++){
        s[c]   += __shfl_xor_sync(0xFFFFFFFFu, s[c],   16);
        ssq[c] += __shfl_xor_sync(0xFFFFFFFFu, ssq[c], 16);
    }
    __syncthreads();                          // all sP2/sP1/Dsm reads done
    float* part = (float*)(smem + QOFF_SP2);  // [8 warps][256]: s | ssq
    if(lane < 16){
        #pragma unroll
        for(int c=0;c<8;c++){
            part[wid*256 + tx*8 + c]       = s[c];
            part[wid*256 + 128 + tx*8 + c] = ssq[c];
        }
    }
    __syncthreads();
    if(tid < 128){
        float a = 0.f, b = 0.f;
        #pragma unroll
        for(int w=0;w<8;w++){
            a += part[w*256 + tid];
            b += part[w*256 + 128 + tid];
        }
        atomicAdd(&g_stats1[tid],       (double)a);
        atomicAdd(&g_stats1[128 + tid], (double)b);
    }
}

__global__ void k_fin1(const float* __restrict__ g1, const float* __restrict__ be1){
    int j = threadIdx.x;                      // 128
    double n = (double)NM;
    double su = g_stats1[j], ssq = g_stats1[128 + j];
    g_stats1[j] = 0.0; g_stats1[128 + j] = 0.0;
    double mu = su / n;
    double var = ssq / n - mu*mu;
    float r = rsqrtf((float)var + 1e-5f);
    float sc = g1[j] * r;
    g_sc1[j] = sc;
    g_sh1[j] = be1[j] - (float)mu * sc;
}

// ------- BN1 apply + sigmoid*softplus + sum over M + BN2 stats (fp16 in) ----
__global__ void k_B(){
    __shared__ float part[8][128];
    int tid = threadIdx.x;                    // 256; 32 atoms/block
    int wid = tid >> 5, lane = tid & 31;
    int fg = (tid & 15) * 4;
    int s  = tid >> 4;                        // 0..15, 2 atoms each
    int base = blockIdx.x * 32 + s*2;
    float4 scf = *(const float4*)&g_sc1[fg];
    float4 shf = *(const float4*)&g_sh1[fg];
    float4 scc = *(const float4*)&g_sc1[64+fg];
    float4 shc = *(const float4*)&g_sh1[64+fg];
    float sc_f[4] = {scf.x,scf.y,scf.z,scf.w};
    float sh_f[4] = {shf.x,shf.y,shf.z,shf.w};
    float sc_c[4] = {scc.x,scc.y,scc.z,scc.w};
    float sh_c[4] = {shc.x,shc.y,shc.z,shc.w};

    float ts[4] = {0,0,0,0}, tss[4] = {0,0,0,0};
    #pragma unroll
    for(int a = 0; a < 2; a++){
        int i = base + a;
        const __half* gp = g_gatedh + (size_t)i*Mm*F2;
        float acc[4] = {0,0,0,0};
        #pragma unroll
        for(int m = 0; m < Mm; m++){
            uint2 uf = *(const uint2*)&gp[m*F2 + fg];
            uint2 uc = *(const uint2*)&gp[m*F2 + 64 + fg];
            float2 f01 = __half22float2(*(__half2*)&uf.x);
            float2 f23 = __half22float2(*(__half2*)&uf.y);
            float2 c01 = __half22float2(*(__half2*)&uc.x);
            float2 c23 = __half22float2(*(__half2*)&uc.y);
            float f0[4] = {f01.x, f01.y, f23.x, f23.y};
            float c0[4] = {c01.x, c01.y, c23.x, c23.y};
            #pragma unroll
            for(int c=0;c<4;c++)
                acc[c] += sg(f0[c]*sc_f[c]+sh_f[c]) * sp(c0[c]*sc_c[c]+sh_c[c]);
        }
        *(float4*)&g_summed[i*64 + fg] = make_float4(acc[0],acc[1],acc[2],acc[3]);
        #pragma unroll
        for(int c=0;c<4;c++){ ts[c] += acc[c]; tss[c] += acc[c]*acc[c]; }
    }
    #pragma unroll
    for(int c=0;c<4;c++){
        ts[c]  += __shfl_xor_sync(0xFFFFFFFFu, ts[c],  16);
        tss[c] += __shfl_xor_sync(0xFFFFFFFFu, tss[c], 16);
    }
    if(lane < 16){
        #pragma unroll
        for(int c=0;c<4;c++){
            part[wid][fg + c]      = ts[c];
            part[wid][64 + fg + c] = tss[c];
        }
    }
    __syncthreads();
    if(tid < 64){
        float a = 0.f, b = 0.f;
        #pragma unroll
        for(int w=0;w<8;w++){ a += part[w][tid]; b += part[w][64 + tid]; }
        atomicAdd(&g_stats2[tid],      (double)a);
        atomicAdd(&g_stats2[64 + tid], (double)b);
    }
}

__global__ void k_fin2(const float* __restrict__ g2, const float* __restrict__ be2){
    int j = threadIdx.x;                      // 64
    double n = (double)Nn;
    double su = g_stats2[j], ssq = g_stats2[64 + j];
    g_stats2[j] = 0.0; g_stats2[64 + j] = 0.0;
    double mu = su / n;
    double var = ssq / n - mu*mu;
    float r = rsqrtf((float)var + 1e-5f);
    float sc = g2[j] * r;
    g_sc2[j] = sc;
    g_sh2[j] = be2[j] - (float)mu * sc;
}

__global__ void k_upd(){
    int id = blockIdx.x*256 + threadIdx.x;    // N*16 threads (float4 each)
    int i = id >> 4, fg = (id & 15) * 4;
    float4 xv = *(const float4*)&g_x[id*4];
    float4 sv = *(const float4*)&g_summed[id*4];
    float4 sc = *(const float4*)&g_sc2[fg];
    float4 sh = *(const float4*)&g_sh2[fg];
    float4 o;
    o.x = sp(xv.x + sv.x*sc.x + sh.x);
    o.y = sp(xv.y + sv.y*sc.y + sh.y);
    o.z = sp(xv.z + sv.z*sc.z + sh.z);
    o.w = sp(xv.w + sv.w*sc.w + sh.w);
    *(float4*)&g_x[id*4] = o;
    __half2 h0 = __floats2half2_rn(o.x, o.y);
    __half2 h1 = __floats2half2_rn(o.z, o.w);
    int t = i >> 7, r = i & 127;
    unsigned off = SWZ((unsigned)(r*128 + fg*2));
    *(uint2*)((char*)g_xh + (size_t)t*16384 + off) =
        make_uint2(*(unsigned*)&h0, *(unsigned*)&h1);
}

// ---------------- pooling + head ----------------
__global__ void k_pool_zero(){
    int id = blockIdx.x*256 + threadIdx.x;
    if(id < NCc*Ff) g_crys[id] = 0.f;
    else if(id < NCc*Ff + NCc) g_cnt[id - NCc*Ff] = 0.f;
}

__global__ void k_pool(const int* __restrict__ cidx){
    int id = blockIdx.x*256 + threadIdx.x;    // N*64 threads
    int i = id >> 6, f = id & 63;
    int c = cidx[i];
    atomicAdd(&g_crys[c*64 + f], g_x[id]);
    if(f == 0) atomicAdd(&g_cnt[c], 1.f);
}

__global__ void k_head(const float* __restrict__ W_fc, const float* __restrict__ b_fc,
                       const float* __restrict__ W_out, const float* __restrict__ b_out,
                       float* __restrict__ out){
    __shared__ float t[64];
    __shared__ float hred[128];
    int c = blockIdx.x, th = threadIdx.x;     // 128
    if(th < 64){
        float cn = fmaxf(g_cnt[c], 1.f);
        t[th] = sp(g_crys[c*64 + th] / cn);
    }
    __syncthreads();
    float acc = b_fc[th];
    #pragma unroll 4
    for(int f = 0; f < 64; f++) acc += t[f] * W_fc[f*128 + th];
    hred[th] = sp(acc) * W_out[th];
    __syncthreads();
    for(int o = 64; o > 0; o >>= 1){
        if(th < o) hred[th] += hred[th + o];
        __syncthreads();
    }
    if(th == 0) out[c] = hred[0] + b_out[0];
}

// ---------------- launcher ----------------
extern "C" void kernel_launch(void* const* d_in, const int* in_sizes, int n_in,
                              void* d_out, int out_size){
    const float* atom_fea = (const float*)d_in[0];
    const float* nbr_fea  = (const float*)d_in[1];
    const int*   nbr_idx  = (const int*)  d_in[2];
    const int*   cidx     = (const int*)  d_in[3];
    const float* W_emb    = (const float*)d_in[4];
    const float* b_emb    = (const float*)d_in[5];
    const float* W_full   = (const float*)d_in[6];
    const float* b_full   = (const float*)d_in[7];
    const float* g1       = (const float*)d_in[8];
    const float* be1      = (const float*)d_in[9];
    const float* g2       = (const float*)d_in[10];
    const float* be2      = (const float*)d_in[11];
    const float* W_fc     = (const float*)d_in[12];
    const float* b_fc     = (const float*)d_in[13];
    const float* W_out    = (const float*)d_in[14];
    const float* b_out    = (const float*)d_in[15];
    float* out = (float*)d_out;

    cudaFuncSetAttribute(k_Q, cudaFuncAttributeMaxDynamicSharedMemorySize, SMEMQ);

    k_emb<<<Nn/8, 512>>>(atom_fea, W_emb, b_emb);
    k_prep<<<NM/128, 256>>>(nbr_fea);
    k_prepW<<<9, 256>>>(W_full);
    k_x2h<<<(Nn*16)/256, 256>>>();
    k_zero_stats<<<1, 256>>>();

    for(int l = 0; l < 3; l++){
        dim3 gp(NTILE, 2);
        k_P<<<gp, 256>>>(l);
        k_Q<<<NM/128, 256, SMEMQ>>>(nbr_idx, b_full + l*128, l);
        k_fin1<<<1, 128>>>(g1 + l*128, be1 + l*128);
        k_B<<<Nn/32, 256>>>();
        k_fin2<<<1, 64>>>(g2 + l*64, be2 + l*64);
        k_upd<<<(Nn*16)/256, 256>>>();
    }

    k_pool_zero<<<(NCc*Ff + NCc + 255)/256, 256>>>();
    k_pool<<<(Nn*Ff)/256, 256>>>(cidx);
    k_head<<<NCc, 128>>>(W_fc, b_fc, W_out, b_out, out);
}